// round 2
// baseline (speedup 1.0000x reference)
#include <cuda_runtime.h>
#include <math.h>

#define SPAT 65536      // F*T = 256*256
#define KSLICES 16
#define CONV_SMEM (128*132*4 + 128*128*4)   // 133120 bytes

// ---------------- scratch (device globals; no allocation allowed) ----------------
__device__ float g_q[16777216];
__device__ float g_k[16777216];
__device__ float g_v[16777216];
__device__ float g_srp[KSLICES*2*256*256];   // partial sr, layout [slice][b][m][n]
__device__ float g_sip[KSLICES*2*256*256];   // partial si
__device__ float g_a[2*256*256];             // softmax result, layout [b][m][n]
__device__ float g_scale[128];
__device__ float g_shift[128];

// ---------------- complex 1x1 conv as one 128x128 x 65536 GEMM per batch --------
// Y[b*128 + r][s] : r<64 -> real out channel r ; r>=64 -> imag out channel r-64
__global__ void __launch_bounds__(256) conv_kernel(const float* __restrict__ X,
                                                   const float* __restrict__ W6,
                                                   int j, float* __restrict__ Y)
{
    extern __shared__ float sm[];
    float* A_s = sm;               // [cc][o], pitch 132 (k-major, k = input row cc)
    float* B_s = sm + 128*132;     // [cc][s], pitch 128

    const int b  = blockIdx.y;
    const int s0 = blockIdx.x * 128;
    const int tid = threadIdx.x;

    const float* Wr = W6 + (size_t)(j*2 + 0)*4096;
    const float* Wi = W6 + (size_t)(j*2 + 1)*4096;

    // Build combined matrix M (transposed into smem): A_s[cc][o] = M[o][cc]
    for (int idx = tid; idx < 16384; idx += 256) {
        int o  = idx & 127;       // fastest -> conflict-free smem stores
        int cc = idx >> 7;
        int oc = (o & 63)*64 + (cc & 63);
        float val;
        if (o < 64) val = (cc < 64) ?  Wr[oc] : -Wi[oc];
        else        val = (cc < 64) ?  Wi[oc] :  Wr[oc];
        A_s[cc*132 + o] = val;
    }
    // Load input tile: rows cc = (p*64+c), cols s0..s0+127
    const float* Xb = X + (size_t)b * 128 * SPAT;
    #pragma unroll
    for (int it = 0; it < 16; it++) {
        int idx4 = tid + it*256;              // 0..4095
        int row  = idx4 >> 5;
        int c4   = (idx4 & 31) << 2;
        float4 v = *(const float4*)(Xb + (size_t)row*SPAT + s0 + c4);
        *(float4*)(B_s + row*128 + c4) = v;
    }
    __syncthreads();

    const int tx = tid & 15, ty = tid >> 4;
    float acc[8][8];
    #pragma unroll
    for (int i = 0; i < 8; i++)
        #pragma unroll
        for (int q = 0; q < 8; q++) acc[i][q] = 0.f;

    #pragma unroll 4
    for (int k = 0; k < 128; k++) {
        float4 a0 = *(float4*)(A_s + k*132 + ty*4);
        float4 a1 = *(float4*)(A_s + k*132 + 64 + ty*4);
        float4 b0 = *(float4*)(B_s + k*128 + tx*4);
        float4 b1 = *(float4*)(B_s + k*128 + 64 + tx*4);
        float av[8] = {a0.x,a0.y,a0.z,a0.w,a1.x,a1.y,a1.z,a1.w};
        float bv[8] = {b0.x,b0.y,b0.z,b0.w,b1.x,b1.y,b1.z,b1.w};
        #pragma unroll
        for (int i = 0; i < 8; i++)
            #pragma unroll
            for (int q = 0; q < 8; q++) acc[i][q] += av[i]*bv[q];
    }

    float* Yb = Y + (size_t)b * 128 * SPAT;
    #pragma unroll
    for (int i = 0; i < 8; i++) {
        int r = (i < 4) ? (ty*4 + i) : (64 + ty*4 + (i-4));
        float* dst = Yb + (size_t)r*SPAT + s0;
        *(float4*)(dst + tx*4)      = make_float4(acc[i][0],acc[i][1],acc[i][2],acc[i][3]);
        *(float4*)(dst + 64 + tx*4) = make_float4(acc[i][4],acc[i][5],acc[i][6],acc[i][7]);
    }
}

// ---------------- BN stats: one block per (p,c) channel; bias cancels exactly ----
__global__ void __launch_bounds__(256) stats_kernel(const float* __restrict__ Y,
                                                    const float* __restrict__ g_all,
                                                    const float* __restrict__ beta_all,
                                                    int j,
                                                    float* __restrict__ scale,
                                                    float* __restrict__ shift)
{
    __shared__ double ssum[256];
    __shared__ double ssq[256];
    const int pc = blockIdx.x, tid = threadIdx.x;
    double s = 0.0, q = 0.0;
    for (int b = 0; b < 2; b++) {
        const float* base = Y + ((size_t)b*128 + pc)*SPAT;
        for (int i = tid; i < SPAT; i += 256) {
            float v = base[i];
            s += v; q += (double)v*v;
        }
    }
    ssum[tid] = s; ssq[tid] = q; __syncthreads();
    for (int st = 128; st > 0; st >>= 1) {
        if (tid < st) { ssum[tid] += ssum[tid+st]; ssq[tid] += ssq[tid+st]; }
        __syncthreads();
    }
    if (tid == 0) {
        double n   = 2.0 * SPAT;
        double mu  = ssum[0] / n;
        double var = ssq[0] / n - mu*mu;
        double inv = 1.0 / sqrt(var + 1e-5);
        float gg = g_all[j*128 + pc];
        float bb = beta_all[j*128 + pc];
        scale[pc] = (float)(gg * inv);
        shift[pc] = bb - (float)(mu * gg * inv);
    }
}

// ---------------- elementwise normalize + leaky relu -----------------------------
__global__ void __launch_bounds__(256) norm_kernel(float* __restrict__ Y,
                                                   const float* __restrict__ scale,
                                                   const float* __restrict__ shift)
{
    int i = blockIdx.x * blockDim.x + threadIdx.x;     // float4 index, exact grid
    int ch = ((i*4) >> 16) & 127;
    float sc = scale[ch], sh = shift[ch];
    float4 v = *(float4*)(Y + (size_t)i*4);
    float a0 = v.x*sc + sh, a1 = v.y*sc + sh, a2 = v.z*sc + sh, a3 = v.w*sc + sh;
    v.x = fmaxf(a0, 0.01f*a0); v.y = fmaxf(a1, 0.01f*a1);
    v.z = fmaxf(a2, 0.01f*a2); v.w = fmaxf(a3, 0.01f*a3);
    *(float4*)(Y + (size_t)i*4) = v;
}

// ---------------- time-branch scores: contraction over cf (slow axis) ------------
// sr[b][n][m] = sum_cf qr*kr + qi*ki ; si = qi*kr - qr*ki ; stored transposed [m][n]
__global__ void __launch_bounds__(256) score_time_kernel(const float* __restrict__ Qt,
                                                         const float* __restrict__ Kt,
                                                         float* __restrict__ srp,
                                                         float* __restrict__ sip)
{
    __shared__ float Qr[32*64], Qi[32*64], Kr[32*64], Ki[32*64];
    const int mt = blockIdx.x, nt = blockIdx.y;
    const int b  = blockIdx.z / KSLICES, sl = blockIdx.z % KSLICES;
    const int n0 = nt*64, m0 = mt*64;
    const int tid = threadIdx.x, tx = tid & 15, ty = tid >> 4;

    float sr[4][4] = {}, si[4][4] = {};
    const size_t bq0 = (size_t)(b*2 + 0) * 16384 * 256;   // real plane
    const size_t bq1 = (size_t)(b*2 + 1) * 16384 * 256;   // imag plane
    const int cf0 = sl * 1024;

    for (int c0 = cf0; c0 < cf0 + 1024; c0 += 32) {
        #pragma unroll
        for (int u = 0; u < 2; u++) {
            int idx4 = tid + u*256;          // 0..511
            int kk   = idx4 >> 4;
            int col4 = (idx4 & 15) << 2;
            size_t qoff = (size_t)(c0 + kk) * 256;
            *(float4*)(Qr + kk*64 + col4) = *(const float4*)(Qt + bq0 + qoff + n0 + col4);
            *(float4*)(Qi + kk*64 + col4) = *(const float4*)(Qt + bq1 + qoff + n0 + col4);
            *(float4*)(Kr + kk*64 + col4) = *(const float4*)(Kt + bq0 + qoff + m0 + col4);
            *(float4*)(Ki + kk*64 + col4) = *(const float4*)(Kt + bq1 + qoff + m0 + col4);
        }
        __syncthreads();
        #pragma unroll 8
        for (int kk = 0; kk < 32; kk++) {
            float4 q0 = *(float4*)(Qr + kk*64 + ty*4);
            float4 q1 = *(float4*)(Qi + kk*64 + ty*4);
            float4 k0 = *(float4*)(Kr + kk*64 + tx*4);
            float4 k1 = *(float4*)(Ki + kk*64 + tx*4);
            float qrv[4] = {q0.x,q0.y,q0.z,q0.w};
            float qiv[4] = {q1.x,q1.y,q1.z,q1.w};
            float krv[4] = {k0.x,k0.y,k0.z,k0.w};
            float kiv[4] = {k1.x,k1.y,k1.z,k1.w};
            #pragma unroll
            for (int i = 0; i < 4; i++)
                #pragma unroll
                for (int q = 0; q < 4; q++) {
                    sr[i][q] += qrv[i]*krv[q] + qiv[i]*kiv[q];
                    si[i][q] += qiv[i]*krv[q] - qrv[i]*kiv[q];
                }
        }
        __syncthreads();
    }
    // write partials, layout [slice][b][m][n]
    #pragma unroll
    for (int q = 0; q < 4; q++) {
        size_t off = (((size_t)sl*2 + b)*256 + (m0 + tx*4 + q))*256 + n0 + ty*4;
        *(float4*)(srp + off) = make_float4(sr[0][q],sr[1][q],sr[2][q],sr[3][q]);
        *(float4*)(sip + off) = make_float4(si[0][q],si[1][q],si[2][q],si[3][q]);
    }
}

// ---------------- freq-branch scores: contraction over (c,t) (t = fast axis) -----
__global__ void __launch_bounds__(256) score_freq_kernel(const float* __restrict__ Qf,
                                                         const float* __restrict__ Kf,
                                                         float* __restrict__ srp,
                                                         float* __restrict__ sip)
{
    __shared__ float Qr[32*65], Qi[32*65], Kr[32*65], Ki[32*65];
    const int mt = blockIdx.x, nt = blockIdx.y;
    const int b  = blockIdx.z / KSLICES, sl = blockIdx.z % KSLICES;
    const int n0 = nt*64, m0 = mt*64;
    const int tid = threadIdx.x, tx = tid & 15, ty = tid >> 4;

    float sr[4][4] = {}, si[4][4] = {};
    const int c0 = sl * 4;   // 64 channels / 16 slices

    for (int c = c0; c < c0 + 4; c++) {
        const size_t bqr = ((size_t)(b*128) + c) * SPAT;
        const size_t bqi = ((size_t)(b*128) + 64 + c) * SPAT;
        for (int t0 = 0; t0 < 256; t0 += 32) {
            #pragma unroll
            for (int u = 0; u < 2; u++) {
                int idx4 = tid + u*256;
                int t4   = (idx4 & 7) << 2;
                int row  = idx4 >> 3;        // 0..63 (f index within tile)
                float4 a = *(const float4*)(Qf + bqr + (size_t)(n0+row)*256 + t0 + t4);
                float4 bqv = *(const float4*)(Qf + bqi + (size_t)(n0+row)*256 + t0 + t4);
                float4 cv = *(const float4*)(Kf + bqr + (size_t)(m0+row)*256 + t0 + t4);
                float4 dv = *(const float4*)(Kf + bqi + (size_t)(m0+row)*256 + t0 + t4);
                Qr[(t4+0)*65+row]=a.x;  Qr[(t4+1)*65+row]=a.y;  Qr[(t4+2)*65+row]=a.z;  Qr[(t4+3)*65+row]=a.w;
                Qi[(t4+0)*65+row]=bqv.x;Qi[(t4+1)*65+row]=bqv.y;Qi[(t4+2)*65+row]=bqv.z;Qi[(t4+3)*65+row]=bqv.w;
                Kr[(t4+0)*65+row]=cv.x; Kr[(t4+1)*65+row]=cv.y; Kr[(t4+2)*65+row]=cv.z; Kr[(t4+3)*65+row]=cv.w;
                Ki[(t4+0)*65+row]=dv.x; Ki[(t4+1)*65+row]=dv.y; Ki[(t4+2)*65+row]=dv.z; Ki[(t4+3)*65+row]=dv.w;
            }
            __syncthreads();
            #pragma unroll 8
            for (int kk = 0; kk < 32; kk++) {
                float qrv[4], qiv[4], krv[4], kiv[4];
                #pragma unroll
                for (int q = 0; q < 4; q++) {
                    qrv[q] = Qr[kk*65 + ty*4 + q];
                    qiv[q] = Qi[kk*65 + ty*4 + q];
                    krv[q] = Kr[kk*65 + tx*4 + q];
                    kiv[q] = Ki[kk*65 + tx*4 + q];
                }
                #pragma unroll
                for (int i = 0; i < 4; i++)
                    #pragma unroll
                    for (int q = 0; q < 4; q++) {
                        sr[i][q] += qrv[i]*krv[q] + qiv[i]*kiv[q];
                        si[i][q] += qiv[i]*krv[q] - qrv[i]*kiv[q];
                    }
            }
            __syncthreads();
        }
    }
    #pragma unroll
    for (int q = 0; q < 4; q++) {
        size_t off = (((size_t)sl*2 + b)*256 + (m0 + tx*4 + q))*256 + n0 + ty*4;
        *(float4*)(srp + off) = make_float4(sr[0][q],sr[1][q],sr[2][q],sr[3][q]);
        *(float4*)(sip + off) = make_float4(si[0][q],si[1][q],si[2][q],si[3][q]);
    }
}

// ---------------- softmax over query axis n (contiguous thanks to [b][m][n]) -----
__global__ void __launch_bounds__(256) softmax_kernel(const float* __restrict__ srp,
                                                      const float* __restrict__ sip,
                                                      float* __restrict__ A)
{
    __shared__ float red[256];
    const int bm = blockIdx.x;
    const int b = bm >> 8, m = bm & 255;
    const int n = threadIdx.x;
    float sr = 0.f, si = 0.f;
    for (int sl = 0; sl < KSLICES; sl++) {
        size_t off = (((size_t)sl*2 + b)*256 + m)*256 + n;
        sr += srp[off]; si += sip[off];
    }
    float z = sqrtf(sr*sr + si*si);
    red[n] = z; __syncthreads();
    for (int st = 128; st > 0; st >>= 1) {
        if (n < st) red[n] = fmaxf(red[n], red[n+st]);
        __syncthreads();
    }
    float mx = red[0]; __syncthreads();
    float e = expf(z - mx);
    red[n] = e; __syncthreads();
    for (int st = 128; st > 0; st >>= 1) {
        if (n < st) red[n] += red[n+st];
        __syncthreads();
    }
    A[((size_t)b*256 + m)*256 + n] = e / red[0];
}

// ---------------- time-branch output: C[row][n] = sum_m V[row][m] * A[b][m][n] ---
__global__ void __launch_bounds__(256) out_time_kernel(const float* __restrict__ V,
                                                       const float* __restrict__ A,
                                                       float* __restrict__ out)
{
    __shared__ float Vs[32*65];   // [m][row] transposed
    __shared__ float As[32*64];   // [m][n]
    const int rt = blockIdx.x, nt = blockIdx.y, b = blockIdx.z;
    const int r0 = rt*64, n0 = nt*64;
    const int tid = threadIdx.x, tx = tid & 15, ty = tid >> 4;
    float acc[4][4] = {};

    for (int m0 = 0; m0 < 256; m0 += 32) {
        #pragma unroll
        for (int u = 0; u < 2; u++) {
            int idx4 = tid + u*256;
            int kk   = idx4 >> 4;
            int col4 = (idx4 & 15) << 2;
            *(float4*)(As + kk*64 + col4) =
                *(const float4*)(A + ((size_t)b*256 + m0 + kk)*256 + n0 + col4);
            int t4  = (idx4 & 7) << 2;
            int row = idx4 >> 3;
            float4 v = *(const float4*)(V + (size_t)(b*32768 + r0 + row)*256 + m0 + t4);
            Vs[(t4+0)*65+row]=v.x; Vs[(t4+1)*65+row]=v.y; Vs[(t4+2)*65+row]=v.z; Vs[(t4+3)*65+row]=v.w;
        }
        __syncthreads();
        #pragma unroll 8
        for (int kk = 0; kk < 32; kk++) {
            float vv[4];
            #pragma unroll
            for (int i = 0; i < 4; i++) vv[i] = Vs[kk*65 + ty*4 + i];
            float4 a4 = *(float4*)(As + kk*64 + tx*4);
            float av[4] = {a4.x,a4.y,a4.z,a4.w};
            #pragma unroll
            for (int i = 0; i < 4; i++)
                #pragma unroll
                for (int q = 0; q < 4; q++) acc[i][q] += vv[i]*av[q];
        }
        __syncthreads();
    }
    #pragma unroll
    for (int i = 0; i < 4; i++)
        *(float4*)(out + (size_t)(b*32768 + r0 + ty*4 + i)*256 + n0 + tx*4) =
            make_float4(acc[i][0],acc[i][1],acc[i][2],acc[i][3]);
}

// ---------------- freq-branch output: of[f][t] = sum_m A[b][m][f] * V[m][t], += --
__global__ void __launch_bounds__(256) out_freq_kernel(const float* __restrict__ V,
                                                       const float* __restrict__ A,
                                                       float* __restrict__ out)
{
    __shared__ float As[32*64];   // [m][f]
    __shared__ float Vs[32*64];   // [m][t]
    const int ft = blockIdx.x >> 2, tt = blockIdx.x & 3;
    const int bpc = blockIdx.y;
    const int b = bpc >> 7, pc = bpc & 127;
    const int f0 = ft*64, t0 = tt*64;
    const size_t vbase = ((size_t)b*128 + pc) * SPAT;
    const int tid = threadIdx.x, tx = tid & 15, ty = tid >> 4;
    float acc[4][4] = {};

    for (int m0 = 0; m0 < 256; m0 += 32) {
        #pragma unroll
        for (int u = 0; u < 2; u++) {
            int idx4 = tid + u*256;
            int kk   = idx4 >> 4;
            int col4 = (idx4 & 15) << 2;
            *(float4*)(As + kk*64 + col4) =
                *(const float4*)(A + ((size_t)b*256 + m0 + kk)*256 + f0 + col4);
            *(float4*)(Vs + kk*64 + col4) =
                *(const float4*)(V + vbase + (size_t)(m0 + kk)*256 + t0 + col4);
        }
        __syncthreads();
        #pragma unroll 8
        for (int kk = 0; kk < 32; kk++) {
            float4 a4 = *(float4*)(As + kk*64 + ty*4);
            float4 v4 = *(float4*)(Vs + kk*64 + tx*4);
            float av[4] = {a4.x,a4.y,a4.z,a4.w};
            float vv[4] = {v4.x,v4.y,v4.z,v4.w};
            #pragma unroll
            for (int i = 0; i < 4; i++)
                #pragma unroll
                for (int q = 0; q < 4; q++) acc[i][q] += av[i]*vv[q];
        }
        __syncthreads();
    }
    #pragma unroll
    for (int i = 0; i < 4; i++) {
        float* dst = out + vbase + (size_t)(f0 + ty*4 + i)*256 + t0 + tx*4;
        float4 old = *(float4*)dst;
        old.x += acc[i][0]; old.y += acc[i][1]; old.z += acc[i][2]; old.w += acc[i][3];
        *(float4*)dst = old;
    }
}

// ---------------- host launch ---------------------------------------------------
extern "C" void kernel_launch(void* const* d_in, const int* in_sizes, int n_in,
                              void* d_out, int out_size)
{
    const float* P    = (const float*)d_in[0];
    const float* Q    = (const float*)d_in[1];
    const float* W    = (const float*)d_in[2];
    // d_in[3] = bias: cancels exactly under BN mean subtraction -> unused
    const float* g    = (const float*)d_in[4];
    const float* beta = (const float*)d_in[5];
    float* out = (float*)d_out;

    float *qp, *kp, *vp, *srp, *sip, *ap, *scp, *shp;
    cudaGetSymbolAddress((void**)&qp,  g_q);
    cudaGetSymbolAddress((void**)&kp,  g_k);
    cudaGetSymbolAddress((void**)&vp,  g_v);
    cudaGetSymbolAddress((void**)&srp, g_srp);
    cudaGetSymbolAddress((void**)&sip, g_sip);
    cudaGetSymbolAddress((void**)&ap,  g_a);
    cudaGetSymbolAddress((void**)&scp, g_scale);
    cudaGetSymbolAddress((void**)&shp, g_shift);

    cudaFuncSetAttribute(conv_kernel, cudaFuncAttributeMaxDynamicSharedMemorySize, CONV_SMEM);

    auto conv_bn_act = [&](const float* X, int j, float* Y) {
        conv_kernel<<<dim3(512, 2), 256, CONV_SMEM>>>(X, W, j, Y);
        stats_kernel<<<128, 256>>>(Y, g, beta, j, scp, shp);
        norm_kernel<<<16384, 256>>>(Y, scp, shp);
    };

    // ---- time branch ----
    conv_bn_act(Q, 0, qp);
    conv_bn_act(P, 1, kp);
    conv_bn_act(P, 2, vp);
    score_time_kernel<<<dim3(4, 4, 2*KSLICES), 256>>>(qp, kp, srp, sip);
    softmax_kernel<<<512, 256>>>(srp, sip, ap);
    out_time_kernel<<<dim3(512, 4, 2), 256>>>(vp, ap, out);

    // ---- freq branch ----
    conv_bn_act(Q, 3, qp);
    conv_bn_act(P, 4, kp);
    conv_bn_act(P, 5, vp);
    score_freq_kernel<<<dim3(4, 4, 2*KSLICES), 256>>>(qp, kp, srp, sip);
    softmax_kernel<<<512, 256>>>(srp, sip, ap);
    out_freq_kernel<<<dim3(16, 256), 256>>>(vp, ap, out);
}

// round 3
// speedup vs baseline: 1.0522x; 1.0522x over previous
#include <cuda_runtime.h>
#include <math.h>

#define SPAT 65536      // F*T = 256*256
#define KSLICES 32
#define CONV_SMEM (128*132*4 + 2*16*256*4)   // 67584 + 32768 = 100352 bytes

// ---------------- scratch (device globals; no allocation allowed) ----------------
__device__ float g_q[16777216];
__device__ float g_k[16777216];
__device__ float g_v[16777216];
__device__ float g_qt[16777216];             // transposed freq Q
__device__ float g_kt[16777216];             // transposed freq K
__device__ float g_srp[KSLICES*2*256*256];   // partial sr, layout [slice][b][m][n]
__device__ float g_sip[KSLICES*2*256*256];   // partial si
__device__ float g_a[2*256*256];             // softmax result, layout [b][m][n]
__device__ float g_scale6[6*128];
__device__ float g_shift6[6*128];

// ---------------- complex 1x1 conv as one 128x128 x 65536 GEMM per batch --------
// Y[b*128 + r][s] : r<64 -> real out channel r ; r>=64 -> imag out channel r-64
// 512 threads, tile M=128 x N=256, 8x8 per thread, double-buffered k-chunks of 16
__global__ void __launch_bounds__(512) conv_kernel(const float* __restrict__ X,
                                                   const float* __restrict__ W6,
                                                   int j, float* __restrict__ Y)
{
    extern __shared__ float sm[];
    float* A_s = sm;               // [k:128][o:128], pitch 132
    float* B_s = sm + 128*132;     // [2][16][256]

    const int b  = blockIdx.y;
    const int s0 = blockIdx.x * 256;
    const int tid = threadIdx.x;

    const float* Wr = W6 + (size_t)(j*2 + 0)*4096;
    const float* Wi = W6 + (size_t)(j*2 + 1)*4096;

    // Build combined matrix M (k-major): A_s[cc][o] = M[o][cc]
    for (int idx = tid; idx < 16384; idx += 512) {
        int o  = idx & 127;
        int cc = idx >> 7;
        int oc = (o & 63)*64 + (cc & 63);
        float val;
        if (o < 64) val = (cc < 64) ?  Wr[oc] : -Wi[oc];
        else        val = (cc < 64) ?  Wi[oc] :  Wr[oc];
        A_s[cc*132 + o] = val;
    }

    const float* Xb = X + (size_t)b * 128 * SPAT;
    const int r0a = tid >> 6,        c0a = (tid & 63) << 2;          // chunk-load slot A
    const int r0b = (tid + 512) >> 6, c0b = ((tid + 512) & 63) << 2; // chunk-load slot B

    float4 pf0, pf1;
    // chunk 0
    pf0 = *(const float4*)(Xb + (size_t)(r0a)*SPAT + s0 + c0a);
    pf1 = *(const float4*)(Xb + (size_t)(r0b)*SPAT + s0 + c0b);
    *(float4*)(B_s + r0a*256 + c0a) = pf0;
    *(float4*)(B_s + r0b*256 + c0b) = pf1;
    __syncthreads();

    const int tx = tid & 31, ty = tid >> 5;
    float acc[8][8];
    #pragma unroll
    for (int i = 0; i < 8; i++)
        #pragma unroll
        for (int q = 0; q < 8; q++) acc[i][q] = 0.f;

    for (int c = 0; c < 8; c++) {
        if (c < 7) {
            int k0 = (c+1)*16;
            pf0 = *(const float4*)(Xb + (size_t)(k0 + r0a)*SPAT + s0 + c0a);
            pf1 = *(const float4*)(Xb + (size_t)(k0 + r0b)*SPAT + s0 + c0b);
        }
        const float* Bc = B_s + (c & 1)*4096;
        #pragma unroll 4
        for (int kk = 0; kk < 16; kk++) {
            int k = c*16 + kk;
            float4 a0 = *(const float4*)(A_s + k*132 + ty*4);
            float4 a1 = *(const float4*)(A_s + k*132 + 64 + ty*4);
            float4 b0 = *(const float4*)(Bc + kk*256 + tx*4);
            float4 b1 = *(const float4*)(Bc + kk*256 + 128 + tx*4);
            float av[8] = {a0.x,a0.y,a0.z,a0.w,a1.x,a1.y,a1.z,a1.w};
            float bv[8] = {b0.x,b0.y,b0.z,b0.w,b1.x,b1.y,b1.z,b1.w};
            #pragma unroll
            for (int i = 0; i < 8; i++)
                #pragma unroll
                for (int q = 0; q < 8; q++) acc[i][q] += av[i]*bv[q];
        }
        if (c < 7) {
            float* Bn = B_s + ((c+1) & 1)*4096;
            *(float4*)(Bn + r0a*256 + c0a) = pf0;
            *(float4*)(Bn + r0b*256 + c0b) = pf1;
        }
        __syncthreads();
    }

    float* Yb = Y + (size_t)b * 128 * SPAT;
    #pragma unroll
    for (int i = 0; i < 8; i++) {
        int r = (i < 4) ? (ty*4 + i) : (64 + ty*4 + (i-4));
        float* dst = Yb + (size_t)r*SPAT + s0;
        *(float4*)(dst + tx*4)       = make_float4(acc[i][0],acc[i][1],acc[i][2],acc[i][3]);
        *(float4*)(dst + 128 + tx*4) = make_float4(acc[i][4],acc[i][5],acc[i][6],acc[i][7]);
    }
}

// ---------------- BN stats: one block per (p,c) channel; bias cancels exactly ----
__global__ void __launch_bounds__(256) stats_kernel(const float* __restrict__ Y,
                                                    const float* __restrict__ g_all,
                                                    const float* __restrict__ beta_all,
                                                    int j,
                                                    float* __restrict__ scale6,
                                                    float* __restrict__ shift6)
{
    __shared__ double ssum[256];
    __shared__ double ssq[256];
    const int pc = blockIdx.x, tid = threadIdx.x;
    double s = 0.0, q = 0.0;
    for (int b = 0; b < 2; b++) {
        const float4* base = (const float4*)(Y + ((size_t)b*128 + pc)*SPAT);
        for (int i = tid; i < SPAT/4; i += 256) {
            float4 v = base[i];
            s += (double)v.x + (double)v.y + (double)v.z + (double)v.w;
            q += (double)v.x*v.x + (double)v.y*v.y + (double)v.z*v.z + (double)v.w*v.w;
        }
    }
    ssum[tid] = s; ssq[tid] = q; __syncthreads();
    for (int st = 128; st > 0; st >>= 1) {
        if (tid < st) { ssum[tid] += ssum[tid+st]; ssq[tid] += ssq[tid+st]; }
        __syncthreads();
    }
    if (tid == 0) {
        double n   = 2.0 * SPAT;
        double mu  = ssum[0] / n;
        double var = ssq[0] / n - mu*mu;
        double inv = 1.0 / sqrt(var + 1e-5);
        float gg = g_all[j*128 + pc];
        float bb = beta_all[j*128 + pc];
        scale6[j*128 + pc] = (float)(gg * inv);
        shift6[j*128 + pc] = bb - (float)(mu * gg * inv);
    }
}

// ---------------- elementwise normalize + leaky relu -----------------------------
__global__ void __launch_bounds__(256) norm_kernel(float* __restrict__ Y,
                                                   const float* __restrict__ scale,
                                                   const float* __restrict__ shift)
{
    int i = blockIdx.x * blockDim.x + threadIdx.x;     // float4 index, exact grid
    int ch = ((i*4) >> 16) & 127;
    float sc = scale[ch], sh = shift[ch];
    float4 v = *(float4*)(Y + (size_t)i*4);
    float a0 = v.x*sc + sh, a1 = v.y*sc + sh, a2 = v.z*sc + sh, a3 = v.w*sc + sh;
    v.x = fmaxf(a0, 0.01f*a0); v.y = fmaxf(a1, 0.01f*a1);
    v.z = fmaxf(a2, 0.01f*a2); v.w = fmaxf(a3, 0.01f*a3);
    *(float4*)(Y + (size_t)i*4) = v;
}

// ---------------- fused transpose + norm + leaky (freq Q/K): [f][t] -> [t][f] ----
// in plane (b,p,c): Y[plane][f*256+t]  ->  out[(b,p)][c*256+t][f]
__global__ void __launch_bounds__(256) tnorm_kernel(const float* __restrict__ Y,
                                                    float* __restrict__ out,
                                                    const float* __restrict__ scale6,
                                                    const float* __restrict__ shift6,
                                                    int j)
{
    __shared__ float sm[32][33];
    const int plane = blockIdx.z;                 // b*128 + p*64 + c
    const int pc = plane & 127;
    const float sc = scale6[j*128 + pc], sh = shift6[j*128 + pc];
    const int t0 = blockIdx.x*32, f0 = blockIdx.y*32;
    const int tx = threadIdx.x & 31, ty = threadIdx.x >> 5;   // ty 0..7
    const float* ip = Y + (size_t)plane*SPAT;
    #pragma unroll
    for (int jj = 0; jj < 4; jj++) {
        float v = ip[(size_t)(f0 + ty + 8*jj)*256 + t0 + tx];
        v = v*sc + sh;
        v = fmaxf(v, 0.01f*v);
        sm[ty + 8*jj][tx] = v;
    }
    __syncthreads();
    const int b = plane >> 7, p = (plane >> 6) & 1, c = plane & 63;
    float* op = out + (((size_t)(b*2 + p)*16384 + c*256) * 256);
    #pragma unroll
    for (int jj = 0; jj < 4; jj++)
        op[(size_t)(t0 + ty + 8*jj)*256 + f0 + tx] = sm[tx][ty + 8*jj];
}

// ---------------- unified score kernel: layout [(b,p)][k:16384][256] -------------
// out[m][n] partial (transposed): sr = qr[n]kr[m]+qi[n]ki[m], si = qi[n]kr[m]-qr[n]ki[m]
// 128x128 tile, 256 threads, 8x8 complex per thread, k-chunks of 16
__global__ void __launch_bounds__(256) score_kernel(const float* __restrict__ Qt,
                                                    const float* __restrict__ Kt,
                                                    float* __restrict__ srp,
                                                    float* __restrict__ sip)
{
    __shared__ float Qr[16*128], Qi[16*128], Kr[16*128], Ki[16*128];
    const int bz = blockIdx.z;
    const int b = bz >> 5, sl = bz & 31;
    const int m0 = blockIdx.x*128, n0 = blockIdx.y*128;
    const int tid = threadIdx.x, tx = tid & 15, ty = tid >> 4;
    const size_t bq0 = (size_t)(b*2 + 0) * 16384 * 256;
    const size_t bq1 = (size_t)(b*2 + 1) * 16384 * 256;
    const int kbase = sl * 512;

    float sr[8][8], si[8][8];
    #pragma unroll
    for (int i = 0; i < 8; i++)
        #pragma unroll
        for (int q = 0; q < 8; q++) { sr[i][q] = 0.f; si[i][q] = 0.f; }

    for (int c = 0; c < 32; c++) {
        __syncthreads();
        const int k0 = kbase + c*16;
        #pragma unroll
        for (int u = 0; u < 2; u++) {
            int idx4 = tid + u*256;
            int kk   = idx4 >> 5;
            int col4 = (idx4 & 31) << 2;
            size_t roff = (size_t)(k0 + kk) * 256;
            *(float4*)(Qr + kk*128 + col4) = *(const float4*)(Qt + bq0 + roff + n0 + col4);
            *(float4*)(Qi + kk*128 + col4) = *(const float4*)(Qt + bq1 + roff + n0 + col4);
            *(float4*)(Kr + kk*128 + col4) = *(const float4*)(Kt + bq0 + roff + m0 + col4);
            *(float4*)(Ki + kk*128 + col4) = *(const float4*)(Kt + bq1 + roff + m0 + col4);
        }
        __syncthreads();
        #pragma unroll 2
        for (int kk = 0; kk < 16; kk++) {
            float4 q0 = *(const float4*)(Qr + kk*128 + tx*4);
            float4 q1 = *(const float4*)(Qr + kk*128 + 64 + tx*4);
            float4 q2 = *(const float4*)(Qi + kk*128 + tx*4);
            float4 q3 = *(const float4*)(Qi + kk*128 + 64 + tx*4);
            float4 k0v = *(const float4*)(Kr + kk*128 + ty*4);
            float4 k1v = *(const float4*)(Kr + kk*128 + 64 + ty*4);
            float4 k2v = *(const float4*)(Ki + kk*128 + ty*4);
            float4 k3v = *(const float4*)(Ki + kk*128 + 64 + ty*4);
            float qrv[8] = {q0.x,q0.y,q0.z,q0.w,q1.x,q1.y,q1.z,q1.w};
            float qiv[8] = {q2.x,q2.y,q2.z,q2.w,q3.x,q3.y,q3.z,q3.w};
            float krv[8] = {k0v.x,k0v.y,k0v.z,k0v.w,k1v.x,k1v.y,k1v.z,k1v.w};
            float kiv[8] = {k2v.x,k2v.y,k2v.z,k2v.w,k3v.x,k3v.y,k3v.z,k3v.w};
            #pragma unroll
            for (int i = 0; i < 8; i++)
                #pragma unroll
                for (int q = 0; q < 8; q++) {
                    sr[i][q] += krv[i]*qrv[q] + kiv[i]*qiv[q];
                    si[i][q] += krv[i]*qiv[q] - kiv[i]*qrv[q];
                }
        }
    }
    // write partials, layout [slice][b][m][n]
    #pragma unroll
    for (int i = 0; i < 8; i++) {
        int m = (i < 4) ? (m0 + ty*4 + i) : (m0 + 64 + ty*4 + (i-4));
        size_t off = (((size_t)sl*2 + b)*256 + m)*256 + n0;
        *(float4*)(srp + off + tx*4)      = make_float4(sr[i][0],sr[i][1],sr[i][2],sr[i][3]);
        *(float4*)(srp + off + 64 + tx*4) = make_float4(sr[i][4],sr[i][5],sr[i][6],sr[i][7]);
        *(float4*)(sip + off + tx*4)      = make_float4(si[i][0],si[i][1],si[i][2],si[i][3]);
        *(float4*)(sip + off + 64 + tx*4) = make_float4(si[i][4],si[i][5],si[i][6],si[i][7]);
    }
}

// ---------------- softmax over query axis n (contiguous thanks to [b][m][n]) -----
__global__ void __launch_bounds__(256) softmax_kernel(const float* __restrict__ srp,
                                                      const float* __restrict__ sip,
                                                      float* __restrict__ A)
{
    __shared__ float red[256];
    const int bm = blockIdx.x;
    const int b = bm >> 8, m = bm & 255;
    const int n = threadIdx.x;
    float sr = 0.f, si = 0.f;
    for (int sl = 0; sl < KSLICES; sl++) {
        size_t off = (((size_t)sl*2 + b)*256 + m)*256 + n;
        sr += srp[off]; si += sip[off];
    }
    float z = sqrtf(sr*sr + si*si);
    red[n] = z; __syncthreads();
    for (int st = 128; st > 0; st >>= 1) {
        if (n < st) red[n] = fmaxf(red[n], red[n+st]);
        __syncthreads();
    }
    float mx = red[0]; __syncthreads();
    float e = expf(z - mx);
    red[n] = e; __syncthreads();
    for (int st = 128; st > 0; st >>= 1) {
        if (n < st) red[n] += red[n+st];
        __syncthreads();
    }
    A[((size_t)b*256 + m)*256 + n] = e / red[0];
}

// ---------------- time-branch output: C[r][n] = sum_m V[r][m] * A[b][m][n] -------
// tile 128 rows x 128 n, 256 threads, 8x8, k-chunks of 32
__global__ void __launch_bounds__(256) out_time_kernel(const float* __restrict__ V,
                                                       const float* __restrict__ A,
                                                       float* __restrict__ out)
{
    __shared__ float Vs[32*132];   // [m][row] transposed, pitch 132
    __shared__ float As[32*128];   // [m][n]
    const int r0 = blockIdx.x*128, n0 = blockIdx.y*128, b = blockIdx.z;
    const int tid = threadIdx.x, tx = tid & 15, ty = tid >> 4;
    float acc[8][8];
    #pragma unroll
    for (int i = 0; i < 8; i++)
        #pragma unroll
        for (int q = 0; q < 8; q++) acc[i][q] = 0.f;

    for (int c = 0; c < 8; c++) {
        __syncthreads();
        const int m0c = c*32;
        #pragma unroll
        for (int u = 0; u < 4; u++) {
            int idx4 = tid + u*256;
            // As: [kk][col]
            int kk   = idx4 >> 5;
            int col4 = (idx4 & 31) << 2;
            *(float4*)(As + kk*128 + col4) =
                *(const float4*)(A + ((size_t)b*256 + m0c + kk)*256 + n0 + col4);
            // Vs transposed: mg fast for coalescing
            int mg  = idx4 & 7;
            int row = idx4 >> 3;
            float4 v = *(const float4*)(V + (size_t)(b*32768 + r0 + row)*256 + m0c + mg*4);
            Vs[(mg*4+0)*132 + row] = v.x;
            Vs[(mg*4+1)*132 + row] = v.y;
            Vs[(mg*4+2)*132 + row] = v.z;
            Vs[(mg*4+3)*132 + row] = v.w;
        }
        __syncthreads();
        #pragma unroll 4
        for (int kk = 0; kk < 32; kk++) {
            float4 v0 = *(const float4*)(Vs + kk*132 + ty*4);
            float4 v1 = *(const float4*)(Vs + kk*132 + 64 + ty*4);
            float4 a0 = *(const float4*)(As + kk*128 + tx*4);
            float4 a1 = *(const float4*)(As + kk*128 + 64 + tx*4);
            float vv[8] = {v0.x,v0.y,v0.z,v0.w,v1.x,v1.y,v1.z,v1.w};
            float av[8] = {a0.x,a0.y,a0.z,a0.w,a1.x,a1.y,a1.z,a1.w};
            #pragma unroll
            for (int i = 0; i < 8; i++)
                #pragma unroll
                for (int q = 0; q < 8; q++) acc[i][q] += vv[i]*av[q];
        }
    }
    #pragma unroll
    for (int i = 0; i < 8; i++) {
        int r = (i < 4) ? (r0 + ty*4 + i) : (r0 + 64 + ty*4 + (i-4));
        float* dst = out + (size_t)(b*32768 + r)*256 + n0;
        *(float4*)(dst + tx*4)      = make_float4(acc[i][0],acc[i][1],acc[i][2],acc[i][3]);
        *(float4*)(dst + 64 + tx*4) = make_float4(acc[i][4],acc[i][5],acc[i][6],acc[i][7]);
    }
}

// ---------------- freq-branch output: of[f][t] += sum_m A[b][m][f] * Vp[m][t] ----
// per plane (b,pc): 128x128 tiles, 8x8 per thread, k-chunks of 32
__global__ void __launch_bounds__(256) out_freq_kernel(const float* __restrict__ V,
                                                       const float* __restrict__ A,
                                                       float* __restrict__ out)
{
    __shared__ float As[32*128];   // [m][f]
    __shared__ float Vs[32*128];   // [m][t]
    const int f0 = (blockIdx.x >> 1)*128, t0 = (blockIdx.x & 1)*128;
    const int plane = blockIdx.y;               // b*128 + pc
    const int b = plane >> 7;
    const size_t vbase = (size_t)plane * SPAT;
    const int tid = threadIdx.x, tx = tid & 15, ty = tid >> 4;
    float acc[8][8];
    #pragma unroll
    for (int i = 0; i < 8; i++)
        #pragma unroll
        for (int q = 0; q < 8; q++) acc[i][q] = 0.f;

    for (int c = 0; c < 8; c++) {
        __syncthreads();
        const int m0c = c*32;
        #pragma unroll
        for (int u = 0; u < 4; u++) {
            int idx4 = tid + u*256;
            int kk   = idx4 >> 5;
            int col4 = (idx4 & 31) << 2;
            *(float4*)(As + kk*128 + col4) =
                *(const float4*)(A + ((size_t)b*256 + m0c + kk)*256 + f0 + col4);
            *(float4*)(Vs + kk*128 + col4) =
                *(const float4*)(V + vbase + (size_t)(m0c + kk)*256 + t0 + col4);
        }
        __syncthreads();
        #pragma unroll 4
        for (int kk = 0; kk < 32; kk++) {
            float4 a0 = *(const float4*)(As + kk*128 + ty*4);
            float4 a1 = *(const float4*)(As + kk*128 + 64 + ty*4);
            float4 v0 = *(const float4*)(Vs + kk*128 + tx*4);
            float4 v1 = *(const float4*)(Vs + kk*128 + 64 + tx*4);
            float av[8] = {a0.x,a0.y,a0.z,a0.w,a1.x,a1.y,a1.z,a1.w};
            float vv[8] = {v0.x,v0.y,v0.z,v0.w,v1.x,v1.y,v1.z,v1.w};
            #pragma unroll
            for (int i = 0; i < 8; i++)
                #pragma unroll
                for (int q = 0; q < 8; q++) acc[i][q] += av[i]*vv[q];
        }
    }
    #pragma unroll
    for (int i = 0; i < 8; i++) {
        int f = (i < 4) ? (f0 + ty*4 + i) : (f0 + 64 + ty*4 + (i-4));
        float* dst = out + vbase + (size_t)f*256 + t0;
        float4 o0 = *(float4*)(dst + tx*4);
        float4 o1 = *(float4*)(dst + 64 + tx*4);
        o0.x += acc[i][0]; o0.y += acc[i][1]; o0.z += acc[i][2]; o0.w += acc[i][3];
        o1.x += acc[i][4]; o1.y += acc[i][5]; o1.z += acc[i][6]; o1.w += acc[i][7];
        *(float4*)(dst + tx*4)      = o0;
        *(float4*)(dst + 64 + tx*4) = o1;
    }
}

// ---------------- host launch ---------------------------------------------------
extern "C" void kernel_launch(void* const* d_in, const int* in_sizes, int n_in,
                              void* d_out, int out_size)
{
    const float* P    = (const float*)d_in[0];
    const float* Q    = (const float*)d_in[1];
    const float* W    = (const float*)d_in[2];
    // d_in[3] = bias: cancels exactly under BN mean subtraction -> unused
    const float* g    = (const float*)d_in[4];
    const float* beta = (const float*)d_in[5];
    float* out = (float*)d_out;

    float *qp, *kp, *vp, *qtp, *ktp, *srp, *sip, *ap, *scp, *shp;
    cudaGetSymbolAddress((void**)&qp,  g_q);
    cudaGetSymbolAddress((void**)&kp,  g_k);
    cudaGetSymbolAddress((void**)&vp,  g_v);
    cudaGetSymbolAddress((void**)&qtp, g_qt);
    cudaGetSymbolAddress((void**)&ktp, g_kt);
    cudaGetSymbolAddress((void**)&srp, g_srp);
    cudaGetSymbolAddress((void**)&sip, g_sip);
    cudaGetSymbolAddress((void**)&ap,  g_a);
    cudaGetSymbolAddress((void**)&scp, g_scale6);
    cudaGetSymbolAddress((void**)&shp, g_shift6);

    cudaFuncSetAttribute(conv_kernel, cudaFuncAttributeMaxDynamicSharedMemorySize, CONV_SMEM);

    auto conv_stats = [&](const float* X, int j, float* Y) {
        conv_kernel<<<dim3(256, 2), 512, CONV_SMEM>>>(X, W, j, Y);
        stats_kernel<<<128, 256>>>(Y, g, beta, j, scp, shp);
    };

    // ---- time branch ----
    conv_stats(Q, 0, qp);
    norm_kernel<<<16384, 256>>>(qp, scp + 0*128, shp + 0*128);
    conv_stats(P, 1, kp);
    norm_kernel<<<16384, 256>>>(kp, scp + 1*128, shp + 1*128);
    conv_stats(P, 2, vp);
    norm_kernel<<<16384, 256>>>(vp, scp + 2*128, shp + 2*128);
    score_kernel<<<dim3(2, 2, 2*KSLICES), 256>>>(qp, kp, srp, sip);
    softmax_kernel<<<512, 256>>>(srp, sip, ap);
    out_time_kernel<<<dim3(256, 2, 2), 256>>>(vp, ap, out);

    // ---- freq branch ----
    conv_stats(Q, 3, qp);
    tnorm_kernel<<<dim3(8, 8, 256), 256>>>(qp, qtp, scp, shp, 3);
    conv_stats(P, 4, kp);
    tnorm_kernel<<<dim3(8, 8, 256), 256>>>(kp, ktp, scp, shp, 4);
    conv_stats(P, 5, vp);
    norm_kernel<<<16384, 256>>>(vp, scp + 5*128, shp + 5*128);
    score_kernel<<<dim3(2, 2, 2*KSLICES), 256>>>(qtp, ktp, srp, sip);
    softmax_kernel<<<512, 256>>>(srp, sip, ap);
    out_freq_kernel<<<dim3(4, 256), 256>>>(vp, ap, out);
}

// round 5
// speedup vs baseline: 1.3431x; 1.2764x over previous
#include <cuda_runtime.h>
#include <cuda_bf16.h>
#include <math.h>
#include <stdint.h>

#define SPAT 65536      // F*T = 256*256
#define KSLICES 32
#define CONV_SMEM (128*132*4 + 2*16*256*4)   // 100352 bytes
#define SC2_SMEM  (8*128*80)                 // 81920 bytes

// ---------------- scratch (device globals; no allocation allowed) ----------------
__device__ float g_q[16777216];
__device__ float g_k[16777216];
__device__ float g_v[16777216];
__device__ __nv_bfloat16 g_qhi[16777216];    // [bp:4][row:256][k:16384]
__device__ __nv_bfloat16 g_qlo[16777216];
__device__ __nv_bfloat16 g_khi[16777216];
__device__ __nv_bfloat16 g_klo[16777216];
__device__ float g_srp[KSLICES*2*256*256];   // partial sr, layout [slice][b][m][n]
__device__ float g_sip[KSLICES*2*256*256];
__device__ float g_a[2*256*256];             // softmax result, layout [b][m][n]
__device__ float g_scale6[6*128];
__device__ float g_shift6[6*128];

// ---------------- complex 1x1 conv as one 128x128 x 65536 GEMM per batch --------
__global__ void __launch_bounds__(512) conv_kernel(const float* __restrict__ X,
                                                   const float* __restrict__ W6,
                                                   int j, float* __restrict__ Y)
{
    extern __shared__ float sm[];
    float* A_s = sm;               // [k:128][o:128], pitch 132
    float* B_s = sm + 128*132;     // [2][16][256]

    const int b  = blockIdx.y;
    const int s0 = blockIdx.x * 256;
    const int tid = threadIdx.x;

    const float* Wr = W6 + (size_t)(j*2 + 0)*4096;
    const float* Wi = W6 + (size_t)(j*2 + 1)*4096;

    for (int idx = tid; idx < 16384; idx += 512) {
        int o  = idx & 127;
        int cc = idx >> 7;
        int oc = (o & 63)*64 + (cc & 63);
        float val;
        if (o < 64) val = (cc < 64) ?  Wr[oc] : -Wi[oc];
        else        val = (cc < 64) ?  Wi[oc] :  Wr[oc];
        A_s[cc*132 + o] = val;
    }

    const float* Xb = X + (size_t)b * 128 * SPAT;
    const int r0a = tid >> 6,        c0a = (tid & 63) << 2;
    const int r0b = (tid + 512) >> 6, c0b = ((tid + 512) & 63) << 2;

    float4 pf0, pf1;
    pf0 = *(const float4*)(Xb + (size_t)(r0a)*SPAT + s0 + c0a);
    pf1 = *(const float4*)(Xb + (size_t)(r0b)*SPAT + s0 + c0b);
    *(float4*)(B_s + r0a*256 + c0a) = pf0;
    *(float4*)(B_s + r0b*256 + c0b) = pf1;
    __syncthreads();

    const int tx = tid & 31, ty = tid >> 5;
    float acc[8][8];
    #pragma unroll
    for (int i = 0; i < 8; i++)
        #pragma unroll
        for (int q = 0; q < 8; q++) acc[i][q] = 0.f;

    for (int c = 0; c < 8; c++) {
        if (c < 7) {
            int k0 = (c+1)*16;
            pf0 = *(const float4*)(Xb + (size_t)(k0 + r0a)*SPAT + s0 + c0a);
            pf1 = *(const float4*)(Xb + (size_t)(k0 + r0b)*SPAT + s0 + c0b);
        }
        const float* Bc = B_s + (c & 1)*4096;
        #pragma unroll 4
        for (int kk = 0; kk < 16; kk++) {
            int k = c*16 + kk;
            float4 a0 = *(const float4*)(A_s + k*132 + ty*4);
            float4 a1 = *(const float4*)(A_s + k*132 + 64 + ty*4);
            float4 b0 = *(const float4*)(Bc + kk*256 + tx*4);
            float4 b1 = *(const float4*)(Bc + kk*256 + 128 + tx*4);
            float av[8] = {a0.x,a0.y,a0.z,a0.w,a1.x,a1.y,a1.z,a1.w};
            float bv[8] = {b0.x,b0.y,b0.z,b0.w,b1.x,b1.y,b1.z,b1.w};
            #pragma unroll
            for (int i = 0; i < 8; i++)
                #pragma unroll
                for (int q = 0; q < 8; q++) acc[i][q] += av[i]*bv[q];
        }
        if (c < 7) {
            float* Bn = B_s + ((c+1) & 1)*4096;
            *(float4*)(Bn + r0a*256 + c0a) = pf0;
            *(float4*)(Bn + r0b*256 + c0b) = pf1;
        }
        __syncthreads();
    }

    float* Yb = Y + (size_t)b * 128 * SPAT;
    #pragma unroll
    for (int i = 0; i < 8; i++) {
        int r = (i < 4) ? (ty*4 + i) : (64 + ty*4 + (i-4));
        float* dst = Yb + (size_t)r*SPAT + s0;
        *(float4*)(dst + tx*4)       = make_float4(acc[i][0],acc[i][1],acc[i][2],acc[i][3]);
        *(float4*)(dst + 128 + tx*4) = make_float4(acc[i][4],acc[i][5],acc[i][6],acc[i][7]);
    }
}

// ---------------- BN stats ------------------------------------------------------
__global__ void __launch_bounds__(256) stats_kernel(const float* __restrict__ Y,
                                                    const float* __restrict__ g_all,
                                                    const float* __restrict__ beta_all,
                                                    int j,
                                                    float* __restrict__ scale6,
                                                    float* __restrict__ shift6)
{
    __shared__ double ssum[256];
    __shared__ double ssq[256];
    const int pc = blockIdx.x, tid = threadIdx.x;
    double s = 0.0, q = 0.0;
    for (int b = 0; b < 2; b++) {
        const float4* base = (const float4*)(Y + ((size_t)b*128 + pc)*SPAT);
        for (int i = tid; i < SPAT/4; i += 256) {
            float4 v = base[i];
            s += (double)v.x + (double)v.y + (double)v.z + (double)v.w;
            q += (double)v.x*v.x + (double)v.y*v.y + (double)v.z*v.z + (double)v.w*v.w;
        }
    }
    ssum[tid] = s; ssq[tid] = q; __syncthreads();
    for (int st = 128; st > 0; st >>= 1) {
        if (tid < st) { ssum[tid] += ssum[tid+st]; ssq[tid] += ssq[tid+st]; }
        __syncthreads();
    }
    if (tid == 0) {
        double n   = 2.0 * SPAT;
        double mu  = ssum[0] / n;
        double var = ssq[0] / n - mu*mu;
        double inv = 1.0 / sqrt(var + 1e-5);
        float gg = g_all[j*128 + pc];
        float bb = beta_all[j*128 + pc];
        scale6[j*128 + pc] = (float)(gg * inv);
        shift6[j*128 + pc] = bb - (float)(mu * gg * inv);
    }
}

// ---------------- elementwise normalize + leaky relu (V only) --------------------
__global__ void __launch_bounds__(256) norm_kernel(float* __restrict__ Y,
                                                   const float* __restrict__ scale,
                                                   const float* __restrict__ shift)
{
    int i = blockIdx.x * blockDim.x + threadIdx.x;
    int ch = ((i*4) >> 16) & 127;
    float sc = scale[ch], sh = shift[ch];
    float4 v = *(float4*)(Y + (size_t)i*4);
    float a0 = v.x*sc + sh, a1 = v.y*sc + sh, a2 = v.z*sc + sh, a3 = v.w*sc + sh;
    v.x = fmaxf(a0, 0.01f*a0); v.y = fmaxf(a1, 0.01f*a1);
    v.z = fmaxf(a2, 0.01f*a2); v.w = fmaxf(a3, 0.01f*a3);
    *(float4*)(Y + (size_t)i*4) = v;
}

// ---------------- helpers for bf16 split ----------------------------------------
__device__ __forceinline__ uint32_t pack2(float a, float b) {
    __nv_bfloat16 ha = __float2bfloat16_rn(a);
    __nv_bfloat16 hb = __float2bfloat16_rn(b);
    return (uint32_t)__bfloat16_as_ushort(ha) | ((uint32_t)__bfloat16_as_ushort(hb) << 16);
}
__device__ __forceinline__ float bf_hi(float v) {
    return __bfloat162float(__float2bfloat16_rn(v));
}

// ---------------- freq-branch convert: norm+leaky+split, NO transpose ------------
__global__ void __launch_bounds__(256) convert_noT_kernel(const float* __restrict__ Y,
                                                          __nv_bfloat16* __restrict__ hi,
                                                          __nv_bfloat16* __restrict__ lo,
                                                          const float* __restrict__ sc6,
                                                          const float* __restrict__ sh6,
                                                          int j)
{
    const int plane = blockIdx.y;                 // b*128 + p*64 + c
    const int pc = plane & 127;
    const float sc = sc6[j*128 + pc], sh = sh6[j*128 + pc];
    const int b = plane >> 7, p = (plane >> 6) & 1, c = plane & 63;
    const int bp = b*2 + p;
    const int e0 = (blockIdx.x*256 + threadIdx.x) * 8;
    const int f = e0 >> 8, t = e0 & 255;

    const float* ip = Y + (size_t)plane*SPAT + e0;
    float4 v0 = *(const float4*)ip;
    float4 v1 = *(const float4*)(ip + 4);
    float v[8] = {v0.x,v0.y,v0.z,v0.w,v1.x,v1.y,v1.z,v1.w};
    uint32_t wh[4], wl[4];
    #pragma unroll
    for (int u = 0; u < 4; u++) {
        float a = v[2*u]*sc + sh;   a = fmaxf(a, 0.01f*a);
        float bvv = v[2*u+1]*sc + sh; bvv = fmaxf(bvv, 0.01f*bvv);
        wh[u] = pack2(a, bvv);
        wl[u] = pack2(a - bf_hi(a), bvv - bf_hi(bvv));
    }
    size_t ob = ((size_t)(bp*256 + f))*16384 + c*256 + t;
    *(uint4*)(hi + ob) = make_uint4(wh[0],wh[1],wh[2],wh[3]);
    *(uint4*)(lo + ob) = make_uint4(wl[0],wl[1],wl[2],wl[3]);
}

// ---------------- time-branch convert: norm+leaky+split + f/t transpose ----------
__global__ void __launch_bounds__(256) convert_T_kernel(const float* __restrict__ Y,
                                                        __nv_bfloat16* __restrict__ hi,
                                                        __nv_bfloat16* __restrict__ lo,
                                                        const float* __restrict__ sc6,
                                                        const float* __restrict__ sh6,
                                                        int j)
{
    __shared__ float smt[32][33];
    const int plane = blockIdx.z;
    const int pc = plane & 127;
    const float sc = sc6[j*128 + pc], sh = sh6[j*128 + pc];
    const int f0 = blockIdx.x*32, t0 = blockIdx.y*32;
    const int tid = threadIdx.x;
    const int tx = tid & 31, ty = tid >> 5;       // ty 0..7
    const float* ip = Y + (size_t)plane*SPAT;
    #pragma unroll
    for (int jj = 0; jj < 4; jj++) {
        float v = ip[(size_t)(f0 + ty + 8*jj)*256 + t0 + tx];
        v = v*sc + sh;
        v = fmaxf(v, 0.01f*v);
        smt[ty + 8*jj][tx] = v;
    }
    __syncthreads();
    const int b = plane >> 7, p = (plane >> 6) & 1, c = plane & 63;
    const int bp = b*2 + p;
    const int half = tid >> 7;     // 0 = hi, 1 = lo
    const int idx  = tid & 127;
    const int tt = idx >> 2, fg = idx & 3;
    float v[8];
    #pragma unroll
    for (int u = 0; u < 8; u++) v[u] = smt[fg*8 + u][tt];
    size_t ob = ((size_t)(bp*256 + t0 + tt))*16384 + c*256 + f0 + fg*8;
    if (half == 0) {
        uint32_t w[4];
        #pragma unroll
        for (int u = 0; u < 4; u++) w[u] = pack2(v[2*u], v[2*u+1]);
        *(uint4*)(hi + ob) = make_uint4(w[0],w[1],w[2],w[3]);
    } else {
        uint32_t w[4];
        #pragma unroll
        for (int u = 0; u < 4; u++)
            w[u] = pack2(v[2*u] - bf_hi(v[2*u]), v[2*u+1] - bf_hi(v[2*u+1]));
        *(uint4*)(lo + ob) = make_uint4(w[0],w[1],w[2],w[3]);
    }
}

// ================= mma.sync helpers ==============================================
__device__ __forceinline__ void ldm4(uint32_t* r, uint32_t addr) {
    asm volatile("ldmatrix.sync.aligned.m8n8.x4.shared.b16 {%0,%1,%2,%3}, [%4];"
                 : "=r"(r[0]), "=r"(r[1]), "=r"(r[2]), "=r"(r[3]) : "r"(addr));
}
__device__ __forceinline__ void mma16816(float* c, const uint32_t* a,
                                         uint32_t b0, uint32_t b1) {
    asm volatile(
        "mma.sync.aligned.m16n8k16.row.col.f32.bf16.bf16.f32 "
        "{%0,%1,%2,%3}, {%4,%5,%6,%7}, {%8,%9}, {%0,%1,%2,%3};"
        : "+f"(c[0]), "+f"(c[1]), "+f"(c[2]), "+f"(c[3])
        : "r"(a[0]), "r"(a[1]), "r"(a[2]), "r"(a[3]), "r"(b0), "r"(b1));
}

// ---------------- mma.sync score kernel -----------------------------------------
// CTA tile: M=128(key m) x N=128(query n), K-slice 512 (16 chunks of 32).
// sr[m][n] = Kr.Qr + Ki.Qi ; si[m][n] = Kr.Qi - Ki.Qr (sign irrelevant for softmax)
// bf16 split-3: x.y ~= xh.yh + xh.yl + xl.yh
__global__ void __launch_bounds__(256) score_mma_kernel(
    const __nv_bfloat16* __restrict__ khi_, const __nv_bfloat16* __restrict__ klo_,
    const __nv_bfloat16* __restrict__ qhi_, const __nv_bfloat16* __restrict__ qlo_,
    float* __restrict__ srp, float* __restrict__ sip)
{
    extern __shared__ char smc[];
    const uint32_t smem_base = (uint32_t)__cvta_generic_to_shared(smc);
    const int tid = threadIdx.x, wid = tid >> 5, lane = tid & 31;
    const int m0 = blockIdx.x * 128, n0 = blockIdx.y * 128;
    const int b = blockIdx.z >> 5, sl = blockIdx.z & 31;
    const int warp_m = (wid >> 1) * 32, warp_n = (wid & 1) * 64;

    const size_t PL = (size_t)256 * 16384;
    // tiles: 0 KRh, 1 KRl, 2 KIh, 3 KIl, 4 QRh, 5 QRl, 6 QIh, 7 QIl
    const __nv_bfloat16* srcs[8] = {
        khi_ + (size_t)(b*2+0)*PL + (size_t)m0*16384,
        klo_ + (size_t)(b*2+0)*PL + (size_t)m0*16384,
        khi_ + (size_t)(b*2+1)*PL + (size_t)m0*16384,
        klo_ + (size_t)(b*2+1)*PL + (size_t)m0*16384,
        qhi_ + (size_t)(b*2+0)*PL + (size_t)n0*16384,
        qlo_ + (size_t)(b*2+0)*PL + (size_t)n0*16384,
        qhi_ + (size_t)(b*2+1)*PL + (size_t)n0*16384,
        qlo_ + (size_t)(b*2+1)*PL + (size_t)n0*16384
    };

    // acc[p][fm][fn][4]: p 0=sr 1=si; fm 0..1 (m16); fn 0..7 (n8)
    float acc[2][2][8][4];
    #pragma unroll
    for (int p = 0; p < 2; p++)
        #pragma unroll
        for (int fm = 0; fm < 2; fm++)
            #pragma unroll
            for (int fn = 0; fn < 8; fn++)
                #pragma unroll
                for (int u = 0; u < 4; u++) acc[p][fm][fn][u] = 0.f;

    // ldmatrix lane addressing (pitch = 80 B = 5 x 16B units per row)
    const int a_row = (lane & 7) + ((lane >> 3) & 1) * 8;   // + fm*16 + warp_m
    const int a_uoff = lane >> 4;                           // 0..1
    const int b_row = (lane & 7) + ((lane >> 4) << 3);      // + pn*16 + warp_n
    const int b_uoff = (lane >> 3) & 1;

    const int kbase = sl * 512;
    for (int ch = 0; ch < 16; ch++) {
        const int k0 = kbase + ch*32;
        __syncthreads();
        #pragma unroll
        for (int i = 0; i < 16; i++) {
            int idx = tid + i*256;            // 0..4095
            int t = idx >> 9, rem = idx & 511;
            int row = rem >> 2, u = rem & 3;
            uint4 v = *(const uint4*)(srcs[t] + (size_t)row*16384 + k0 + u*8);
            *(uint4*)(smc + t*10240 + row*80 + u*16) = v;
        }
        __syncthreads();

        #pragma unroll
        for (int ks = 0; ks < 2; ks++) {
            const int ub = ks*2;
            // A fragments for 4 K operands x 2 m-frags
            uint32_t afr[4][2][4];
            #pragma unroll
            for (int t = 0; t < 4; t++)
                #pragma unroll
                for (int fm = 0; fm < 2; fm++) {
                    uint32_t addr = smem_base + t*10240
                                  + (warp_m + fm*16 + a_row)*80 + (ub + a_uoff)*16;
                    ldm4(afr[t][fm], addr);
                }
            // negated KI (for si -= Ki.Qr)
            uint32_t nKI[2][2][4];   // [h/l][fm][4]
            #pragma unroll
            for (int hl = 0; hl < 2; hl++)
                #pragma unroll
                for (int fm = 0; fm < 2; fm++)
                    #pragma unroll
                    for (int u = 0; u < 4; u++)
                        nKI[hl][fm][u] = afr[2+hl][fm][u] ^ 0x80008000u;

            // process 4 Q operands
            #pragma unroll
            for (int qop = 0; qop < 4; qop++) {
                // B fragments: 8 n8-frags via 4 ldmatrix.x4
                uint32_t bfr[8][2];
                #pragma unroll
                for (int pn = 0; pn < 4; pn++) {
                    uint32_t r[4];
                    uint32_t addr = smem_base + (4+qop)*10240
                                  + (warp_n + pn*16 + b_row)*80 + (ub + b_uoff)*16;
                    ldm4(r, addr);
                    bfr[2*pn+0][0] = r[0]; bfr[2*pn+0][1] = r[1];
                    bfr[2*pn+1][0] = r[2]; bfr[2*pn+1][1] = r[3];
                }
                #pragma unroll
                for (int fm = 0; fm < 2; fm++)
                    #pragma unroll
                    for (int fn = 0; fn < 8; fn++) {
                        uint32_t b0 = bfr[fn][0], b1 = bfr[fn][1];
                        if (qop == 0) {          // QRh
                            mma16816(acc[0][fm][fn], afr[0][fm], b0, b1); // Krh -> sr
                            mma16816(acc[0][fm][fn], afr[1][fm], b0, b1); // Krl -> sr
                            mma16816(acc[1][fm][fn], nKI[0][fm], b0, b1); // -Kih -> si
                            mma16816(acc[1][fm][fn], nKI[1][fm], b0, b1); // -Kil -> si
                        } else if (qop == 1) {   // QRl
                            mma16816(acc[0][fm][fn], afr[0][fm], b0, b1); // Krh -> sr
                            mma16816(acc[1][fm][fn], nKI[0][fm], b0, b1); // -Kih -> si
                        } else if (qop == 2) {   // QIh
                            mma16816(acc[0][fm][fn], afr[2][fm], b0, b1); // Kih -> sr
                            mma16816(acc[0][fm][fn], afr[3][fm], b0, b1); // Kil -> sr
                            mma16816(acc[1][fm][fn], afr[0][fm], b0, b1); // Krh -> si
                            mma16816(acc[1][fm][fn], afr[1][fm], b0, b1); // Krl -> si
                        } else {                 // QIl
                            mma16816(acc[0][fm][fn], afr[2][fm], b0, b1); // Kih -> sr
                            mma16816(acc[1][fm][fn], afr[0][fm], b0, b1); // Krh -> si
                        }
                    }
            }
        }
    }

    // epilogue: write partials [slice][b][m][n]
    const int rl = lane >> 2, cl = (lane & 3) * 2;
    #pragma unroll
    for (int fm = 0; fm < 2; fm++)
        #pragma unroll
        for (int fn = 0; fn < 8; fn++) {
            int m = m0 + warp_m + fm*16 + rl;
            int n = n0 + warp_n + fn*8 + cl;
            size_t off = (((size_t)sl*2 + b)*256 + m)*256 + n;
            float* c0 = acc[0][fm][fn];
            float* c1 = acc[1][fm][fn];
            *(float2*)(srp + off)         = make_float2(c0[0], c0[1]);
            *(float2*)(srp + off + 8*256) = make_float2(c0[2], c0[3]);
            *(float2*)(sip + off)         = make_float2(c1[0], c1[1]);
            *(float2*)(sip + off + 8*256) = make_float2(c1[2], c1[3]);
        }
}

// ---------------- softmax over query axis n --------------------------------------
__global__ void __launch_bounds__(256) softmax_kernel(const float* __restrict__ srp,
                                                      const float* __restrict__ sip,
                                                      float* __restrict__ A)
{
    __shared__ float red[256];
    const int bm = blockIdx.x;
    const int b = bm >> 8, m = bm & 255;
    const int n = threadIdx.x;
    float sr = 0.f, si = 0.f;
    for (int sl = 0; sl < KSLICES; sl++) {
        size_t off = (((size_t)sl*2 + b)*256 + m)*256 + n;
        sr += srp[off]; si += sip[off];
    }
    float z = sqrtf(sr*sr + si*si);
    red[n] = z; __syncthreads();
    for (int st = 128; st > 0; st >>= 1) {
        if (n < st) red[n] = fmaxf(red[n], red[n+st]);
        __syncthreads();
    }
    float mx = red[0]; __syncthreads();
    float e = expf(z - mx);
    red[n] = e; __syncthreads();
    for (int st = 128; st > 0; st >>= 1) {
        if (n < st) red[n] += red[n+st];
        __syncthreads();
    }
    A[((size_t)b*256 + m)*256 + n] = e / red[0];
}

// ---------------- time-branch output ---------------------------------------------
__global__ void __launch_bounds__(256) out_time_kernel(const float* __restrict__ V,
                                                       const float* __restrict__ A,
                                                       float* __restrict__ out)
{
    __shared__ float Vs[32*132];
    __shared__ float As[32*128];
    const int r0 = blockIdx.x*128, n0 = blockIdx.y*128, b = blockIdx.z;
    const int tid = threadIdx.x, tx = tid & 15, ty = tid >> 4;
    float acc[8][8];
    #pragma unroll
    for (int i = 0; i < 8; i++)
        #pragma unroll
        for (int q = 0; q < 8; q++) acc[i][q] = 0.f;

    for (int c = 0; c < 8; c++) {
        __syncthreads();
        const int m0c = c*32;
        #pragma unroll
        for (int u = 0; u < 4; u++) {
            int idx4 = tid + u*256;
            int kk   = idx4 >> 5;
            int col4 = (idx4 & 31) << 2;
            *(float4*)(As + kk*128 + col4) =
                *(const float4*)(A + ((size_t)b*256 + m0c + kk)*256 + n0 + col4);
            int mg  = idx4 & 7;
            int row = idx4 >> 3;
            float4 v = *(const float4*)(V + (size_t)(b*32768 + r0 + row)*256 + m0c + mg*4);
            Vs[(mg*4+0)*132 + row] = v.x;
            Vs[(mg*4+1)*132 + row] = v.y;
            Vs[(mg*4+2)*132 + row] = v.z;
            Vs[(mg*4+3)*132 + row] = v.w;
        }
        __syncthreads();
        #pragma unroll 4
        for (int kk = 0; kk < 32; kk++) {
            float4 v0 = *(const float4*)(Vs + kk*132 + ty*4);
            float4 v1 = *(const float4*)(Vs + kk*132 + 64 + ty*4);
            float4 a0 = *(const float4*)(As + kk*128 + tx*4);
            float4 a1 = *(const float4*)(As + kk*128 + 64 + tx*4);
            float vv[8] = {v0.x,v0.y,v0.z,v0.w,v1.x,v1.y,v1.z,v1.w};
            float av[8] = {a0.x,a0.y,a0.z,a0.w,a1.x,a1.y,a1.z,a1.w};
            #pragma unroll
            for (int i = 0; i < 8; i++)
                #pragma unroll
                for (int q = 0; q < 8; q++) acc[i][q] += vv[i]*av[q];
        }
    }
    #pragma unroll
    for (int i = 0; i < 8; i++) {
        int r = (i < 4) ? (r0 + ty*4 + i) : (r0 + 64 + ty*4 + (i-4));
        float* dst = out + (size_t)(b*32768 + r)*256 + n0;
        *(float4*)(dst + tx*4)      = make_float4(acc[i][0],acc[i][1],acc[i][2],acc[i][3]);
        *(float4*)(dst + 64 + tx*4) = make_float4(acc[i][4],acc[i][5],acc[i][6],acc[i][7]);
    }
}

// ---------------- freq-branch output ---------------------------------------------
__global__ void __launch_bounds__(256) out_freq_kernel(const float* __restrict__ V,
                                                       const float* __restrict__ A,
                                                       float* __restrict__ out)
{
    __shared__ float As[32*128];
    __shared__ float Vs[32*128];
    const int f0 = (blockIdx.x >> 1)*128, t0 = (blockIdx.x & 1)*128;
    const int plane = blockIdx.y;
    const int b = plane >> 7;
    const size_t vbase = (size_t)plane * SPAT;
    const int tid = threadIdx.x, tx = tid & 15, ty = tid >> 4;
    float acc[8][8];
    #pragma unroll
    for (int i = 0; i < 8; i++)
        #pragma unroll
        for (int q = 0; q < 8; q++) acc[i][q] = 0.f;

    for (int c = 0; c < 8; c++) {
        __syncthreads();
        const int m0c = c*32;
        #pragma unroll
        for (int u = 0; u < 4; u++) {
            int idx4 = tid + u*256;
            int kk   = idx4 >> 5;
            int col4 = (idx4 & 31) << 2;
            *(float4*)(As + kk*128 + col4) =
                *(const float4*)(A + ((size_t)b*256 + m0c + kk)*256 + f0 + col4);
            *(float4*)(Vs + kk*128 + col4) =
                *(const float4*)(V + vbase + (size_t)(m0c + kk)*256 + t0 + col4);
        }
        __syncthreads();
        #pragma unroll 4
        for (int kk = 0; kk < 32; kk++) {
            float4 a0 = *(const float4*)(As + kk*128 + ty*4);
            float4 a1 = *(const float4*)(As + kk*128 + 64 + ty*4);
            float4 v0 = *(const float4*)(Vs + kk*128 + tx*4);
            float4 v1 = *(const float4*)(Vs + kk*128 + 64 + tx*4);
            float av[8] = {a0.x,a0.y,a0.z,a0.w,a1.x,a1.y,a1.z,a1.w};
            float vv[8] = {v0.x,v0.y,v0.z,v0.w,v1.x,v1.y,v1.z,v1.w};
            #pragma unroll
            for (int i = 0; i < 8; i++)
                #pragma unroll
                for (int q = 0; q < 8; q++) acc[i][q] += av[i]*vv[q];
        }
    }
    #pragma unroll
    for (int i = 0; i < 8; i++) {
        int f = (i < 4) ? (f0 + ty*4 + i) : (f0 + 64 + ty*4 + (i-4));
        float* dst = out + vbase + (size_t)f*256 + t0;
        float4 o0 = *(float4*)(dst + tx*4);
        float4 o1 = *(float4*)(dst + 64 + tx*4);
        o0.x += acc[i][0]; o0.y += acc[i][1]; o0.z += acc[i][2]; o0.w += acc[i][3];
        o1.x += acc[i][4]; o1.y += acc[i][5]; o1.z += acc[i][6]; o1.w += acc[i][7];
        *(float4*)(dst + tx*4)      = o0;
        *(float4*)(dst + 64 + tx*4) = o1;
    }
}

// ---------------- host launch ----------------------------------------------------
extern "C" void kernel_launch(void* const* d_in, const int* in_sizes, int n_in,
                              void* d_out, int out_size)
{
    const float* P    = (const float*)d_in[0];
    const float* Q    = (const float*)d_in[1];
    const float* W    = (const float*)d_in[2];
    // d_in[3] = bias: cancels exactly under BN mean subtraction -> unused
    const float* g    = (const float*)d_in[4];
    const float* beta = (const float*)d_in[5];
    float* out = (float*)d_out;

    float *qp, *kp, *vp, *srp, *sip, *ap, *scp, *shp;
    __nv_bfloat16 *qhi, *qlo, *khi, *klo;
    cudaGetSymbolAddress((void**)&qp,  g_q);
    cudaGetSymbolAddress((void**)&kp,  g_k);
    cudaGetSymbolAddress((void**)&vp,  g_v);
    cudaGetSymbolAddress((void**)&qhi, g_qhi);
    cudaGetSymbolAddress((void**)&qlo, g_qlo);
    cudaGetSymbolAddress((void**)&khi, g_khi);
    cudaGetSymbolAddress((void**)&klo, g_klo);
    cudaGetSymbolAddress((void**)&srp, g_srp);
    cudaGetSymbolAddress((void**)&sip, g_sip);
    cudaGetSymbolAddress((void**)&ap,  g_a);
    cudaGetSymbolAddress((void**)&scp, g_scale6);
    cudaGetSymbolAddress((void**)&shp, g_shift6);

    cudaFuncSetAttribute(conv_kernel, cudaFuncAttributeMaxDynamicSharedMemorySize, CONV_SMEM);
    cudaFuncSetAttribute(score_mma_kernel, cudaFuncAttributeMaxDynamicSharedMemorySize, SC2_SMEM);

    auto conv_stats = [&](const float* X, int j, float* Y) {
        conv_kernel<<<dim3(256, 2), 512, CONV_SMEM>>>(X, W, j, Y);
        stats_kernel<<<128, 256>>>(Y, g, beta, j, scp, shp);
    };

    // ---- time branch ----
    conv_stats(Q, 0, qp);
    convert_T_kernel<<<dim3(8, 8, 256), 256>>>(qp, qhi, qlo, scp, shp, 0);
    conv_stats(P, 1, kp);
    convert_T_kernel<<<dim3(8, 8, 256), 256>>>(kp, khi, klo, scp, shp, 1);
    conv_stats(P, 2, vp);
    norm_kernel<<<16384, 256>>>(vp, scp + 2*128, shp + 2*128);
    score_mma_kernel<<<dim3(2, 2, 64), 256, SC2_SMEM>>>(khi, klo, qhi, qlo, srp, sip);
    softmax_kernel<<<512, 256>>>(srp, sip, ap);
    out_time_kernel<<<dim3(256, 2, 2), 256>>>(vp, ap, out);

    // ---- freq branch ----
    conv_stats(Q, 3, qp);
    convert_noT_kernel<<<dim3(32, 256), 256>>>(qp, qhi, qlo, scp, shp, 3);
    conv_stats(P, 4, kp);
    convert_noT_kernel<<<dim3(32, 256), 256>>>(kp, khi, klo, scp, shp, 4);
    conv_stats(P, 5, vp);
    norm_kernel<<<16384, 256>>>(vp, scp + 5*128, shp + 5*128);
    score_mma_kernel<<<dim3(2, 2, 64), 256, SC2_SMEM>>>(khi, klo, qhi, qlo, srp, sip);
    softmax_kernel<<<512, 256>>>(srp, sip, ap);
    out_freq_kernel<<<dim3(4, 256), 256>>>(vp, ap, out);
}

// round 6
// speedup vs baseline: 2.1915x; 1.6317x over previous
#include <cuda_runtime.h>
#include <cuda_bf16.h>
#include <math.h>
#include <stdint.h>

#define SPAT 65536      // F*T = 256*256
#define KSLICES 32
#define CONV2_SMEM (2*34816 + 2*8704)        // A hi/lo + B hi/lo = 87040 bytes
#define SC2_SMEM   (8*128*80)                // 81920 bytes

// ---------------- scratch (device globals; no allocation allowed) ----------------
__device__ float g_q[16777216];
__device__ float g_k[16777216];
__device__ float g_v[16777216];
__device__ __nv_bfloat16 g_qhi[16777216];    // score operands [bp:4][row:256][k:16384]
__device__ __nv_bfloat16 g_qlo[16777216];
__device__ __nv_bfloat16 g_khi[16777216];
__device__ __nv_bfloat16 g_klo[16777216];
__device__ __nv_bfloat16 g_pshi[16777216];   // split inputs P
__device__ __nv_bfloat16 g_pslo[16777216];
__device__ __nv_bfloat16 g_qshi[16777216];   // split inputs Q
__device__ __nv_bfloat16 g_qslo[16777216];
__device__ __nv_bfloat16 g_wc[6*2*16384];    // combined weights [j][hl][o][cc]
__device__ float g_part[1024*256];           // conv stats partials [cta][row][2]
__device__ float g_srp[KSLICES*2*256*256];   // partial sr, layout [slice][b][m][n]
__device__ float g_sip[KSLICES*2*256*256];
__device__ float g_a[2*256*256];             // softmax result, layout [b][m][n]
__device__ float g_scale6[6*128];
__device__ float g_shift6[6*128];

// ================= mma.sync helpers ==============================================
__device__ __forceinline__ void ldm4(uint32_t* r, uint32_t addr) {
    asm volatile("ldmatrix.sync.aligned.m8n8.x4.shared.b16 {%0,%1,%2,%3}, [%4];"
                 : "=r"(r[0]), "=r"(r[1]), "=r"(r[2]), "=r"(r[3]) : "r"(addr));
}
__device__ __forceinline__ void ldm4t(uint32_t* r, uint32_t addr) {
    asm volatile("ldmatrix.sync.aligned.m8n8.x4.trans.shared.b16 {%0,%1,%2,%3}, [%4];"
                 : "=r"(r[0]), "=r"(r[1]), "=r"(r[2]), "=r"(r[3]) : "r"(addr));
}
__device__ __forceinline__ void mma16816(float* c, const uint32_t* a,
                                         uint32_t b0, uint32_t b1) {
    asm volatile(
        "mma.sync.aligned.m16n8k16.row.col.f32.bf16.bf16.f32 "
        "{%0,%1,%2,%3}, {%4,%5,%6,%7}, {%8,%9}, {%0,%1,%2,%3};"
        : "+f"(c[0]), "+f"(c[1]), "+f"(c[2]), "+f"(c[3])
        : "r"(a[0]), "r"(a[1]), "r"(a[2]), "r"(a[3]), "r"(b0), "r"(b1));
}

// ---------------- helpers for bf16 split ----------------------------------------
__device__ __forceinline__ uint32_t pack2(float a, float b) {
    __nv_bfloat16 ha = __float2bfloat16_rn(a);
    __nv_bfloat16 hb = __float2bfloat16_rn(b);
    return (uint32_t)__bfloat16_as_ushort(ha) | ((uint32_t)__bfloat16_as_ushort(hb) << 16);
}
__device__ __forceinline__ float bf_hi(float v) {
    return __bfloat162float(__float2bfloat16_rn(v));
}

// ---------------- split input fp32 -> bf16 hi/lo ---------------------------------
__global__ void __launch_bounds__(256) split_kernel(const float* __restrict__ X,
                                                    __nv_bfloat16* __restrict__ hi,
                                                    __nv_bfloat16* __restrict__ lo)
{
    size_t i = ((size_t)blockIdx.x*256 + threadIdx.x) * 4;
    float4 v = *(const float4*)(X + i);
    uint2 h, l;
    h.x = pack2(v.x, v.y); h.y = pack2(v.z, v.w);
    l.x = pack2(v.x - bf_hi(v.x), v.y - bf_hi(v.y));
    l.y = pack2(v.z - bf_hi(v.z), v.w - bf_hi(v.w));
    *(uint2*)(hi + i) = h;
    *(uint2*)(lo + i) = l;
}

// ---------------- build combined complex weight matrices (bf16 hi/lo) ------------
__global__ void __launch_bounds__(256) wcomb_kernel(const float* __restrict__ W6,
                                                    __nv_bfloat16* __restrict__ wc)
{
    const int j = blockIdx.y;
    const int idx = blockIdx.x*256 + threadIdx.x;    // 0..16383
    const int o = idx & 127, cc = idx >> 7;
    const float* Wr = W6 + (size_t)(j*2 + 0)*4096;
    const float* Wi = W6 + (size_t)(j*2 + 1)*4096;
    const int oc = (o & 63)*64 + (cc & 63);
    float val;
    if (o < 64) val = (cc < 64) ?  Wr[oc] : -Wi[oc];
    else        val = (cc < 64) ?  Wi[oc] :  Wr[oc];
    float h = bf_hi(val);
    // store [j][hl][o][cc]
    wc[(size_t)j*32768 + o*128 + cc]         = __float2bfloat16_rn(h);
    wc[(size_t)j*32768 + 16384 + o*128 + cc] = __float2bfloat16_rn(val - h);
}

// ---------------- tensor-core conv: Y = M(128x128) @ X(128x65536), per batch -----
// split-3 bf16; also emits per-CTA per-channel (sum, sumsq) partials
__global__ void __launch_bounds__(256) conv_mma_kernel(
    const __nv_bfloat16* __restrict__ Xhi, const __nv_bfloat16* __restrict__ Xlo,
    const __nv_bfloat16* __restrict__ Wc,   // [2][128][128] for this conv
    float* __restrict__ Y, float* __restrict__ part)
{
    extern __shared__ char smb[];
    __shared__ float stats_s[2][128][2];
    const uint32_t sb = (uint32_t)__cvta_generic_to_shared(smb);
    const int tid = threadIdx.x, wid = tid >> 5, lane = tid & 31;
    const int b = blockIdx.y, s0 = blockIdx.x * 128;
    const int warp_m = (wid >> 1) * 32, warp_n = (wid & 1) * 64;
    const int cta = blockIdx.y*512 + blockIdx.x;

    // A smem: [hl][o:128][cc:128] bf16, pitch 272 B
    for (int i = tid; i < 4096; i += 256) {          // uint4 count
        int hl = i >> 11, rem = i & 2047;
        int row = rem >> 4, u = rem & 15;
        uint4 v = *(const uint4*)(Wc + hl*16384 + row*128 + u*8);
        *(uint4*)(smb + hl*34816 + row*272 + u*16) = v;
    }

    float acc[2][8][4];
    #pragma unroll
    for (int fm = 0; fm < 2; fm++)
        #pragma unroll
        for (int fn = 0; fn < 8; fn++)
            #pragma unroll
            for (int u = 0; u < 4; u++) acc[fm][fn][u] = 0.f;

    const __nv_bfloat16* xh = Xhi + (size_t)b*8388608 + s0;
    const __nv_bfloat16* xl = Xlo + (size_t)b*8388608 + s0;

    const int a_row = (lane & 7) + ((lane >> 3) & 1) * 8;
    const int a_u   = lane >> 4;
    const int bt_row = (lane & 7) + ((lane >> 3) & 1) * 8;
    const int bt_c   = (lane >> 4) * 8;

    for (int c = 0; c < 4; c++) {
        __syncthreads();
        // B tiles [hl][k:32][n:128] bf16, pitch 272 B
        for (int i = tid; i < 1024; i += 256) {
            int hl = i >> 9, rem = i & 511;
            int kk = rem >> 4, u = rem & 15;
            uint4 v = *(const uint4*)((hl ? xl : xh) + (size_t)(c*32 + kk)*SPAT + u*8);
            *(uint4*)(smb + 69632 + hl*8704 + kk*272 + u*16) = v;
        }
        __syncthreads();
        #pragma unroll
        for (int ks = 0; ks < 2; ks++) {
            uint32_t Ah[2][4], Al[2][4];
            #pragma unroll
            for (int fm = 0; fm < 2; fm++) {
                uint32_t arow_off = (warp_m + fm*16 + a_row)*272 + c*64 + ks*32 + a_u*16;
                ldm4(Ah[fm], sb + arow_off);
                ldm4(Al[fm], sb + 34816 + arow_off);
            }
            uint32_t Bh[8][2], Bl[8][2];
            #pragma unroll
            for (int fn2 = 0; fn2 < 4; fn2++) {
                uint32_t boff = (ks*16 + bt_row)*272 + (warp_n + fn2*16 + bt_c)*2;
                uint32_t r[4];
                ldm4t(r, sb + 69632 + boff);
                Bh[2*fn2+0][0] = r[0]; Bh[2*fn2+0][1] = r[1];
                Bh[2*fn2+1][0] = r[2]; Bh[2*fn2+1][1] = r[3];
                ldm4t(r, sb + 69632 + 8704 + boff);
                Bl[2*fn2+0][0] = r[0]; Bl[2*fn2+0][1] = r[1];
                Bl[2*fn2+1][0] = r[2]; Bl[2*fn2+1][1] = r[3];
            }
            #pragma unroll
            for (int fm = 0; fm < 2; fm++)
                #pragma unroll
                for (int fn = 0; fn < 8; fn++) {
                    mma16816(acc[fm][fn], Ah[fm], Bh[fn][0], Bh[fn][1]);
                    mma16816(acc[fm][fn], Ah[fm], Bl[fn][0], Bl[fn][1]);
                    mma16816(acc[fm][fn], Al[fm], Bh[fn][0], Bh[fn][1]);
                }
        }
    }

    // epilogue: write Y + per-channel partial stats
    const int rl = lane >> 2, cl = (lane & 3) * 2;
    float* Yb = Y + (size_t)b*8388608;
    float su[2][2] = {}, sq[2][2] = {};
    #pragma unroll
    for (int fm = 0; fm < 2; fm++) {
        int r = warp_m + fm*16 + rl;
        #pragma unroll
        for (int fn = 0; fn < 8; fn++) {
            float* cc4 = acc[fm][fn];
            int ncol = warp_n + fn*8 + cl;
            *(float2*)(Yb + (size_t)r*SPAT + s0 + ncol)     = make_float2(cc4[0], cc4[1]);
            *(float2*)(Yb + (size_t)(r+8)*SPAT + s0 + ncol) = make_float2(cc4[2], cc4[3]);
            su[fm][0] += cc4[0] + cc4[1];
            sq[fm][0] += cc4[0]*cc4[0] + cc4[1]*cc4[1];
            su[fm][1] += cc4[2] + cc4[3];
            sq[fm][1] += cc4[2]*cc4[2] + cc4[3]*cc4[3];
        }
    }
    #pragma unroll
    for (int d = 1; d < 4; d <<= 1)
        #pragma unroll
        for (int fm = 0; fm < 2; fm++)
            #pragma unroll
            for (int h = 0; h < 2; h++) {
                su[fm][h] += __shfl_xor_sync(0xFFFFFFFF, su[fm][h], d);
                sq[fm][h] += __shfl_xor_sync(0xFFFFFFFF, sq[fm][h], d);
            }
    if ((lane & 3) == 0) {
        #pragma unroll
        for (int fm = 0; fm < 2; fm++)
            #pragma unroll
            for (int h = 0; h < 2; h++) {
                int row = warp_m + fm*16 + rl + h*8;
                stats_s[wid & 1][row][0] = su[fm][h];
                stats_s[wid & 1][row][1] = sq[fm][h];
            }
    }
    __syncthreads();
    {
        int row = tid >> 1, cp = tid & 1;
        part[(size_t)cta*256 + tid] =
            stats_s[0][row][cp] + stats_s[1][row][cp];
    }
}

// ---------------- reduce conv partials -> BN scale/shift -------------------------
__global__ void __launch_bounds__(256) stats_reduce_kernel(const float* __restrict__ part,
                                                           const float* __restrict__ g_all,
                                                           const float* __restrict__ beta_all,
                                                           int j,
                                                           float* __restrict__ scale6,
                                                           float* __restrict__ shift6)
{
    __shared__ double ssum[256];
    __shared__ double ssq[256];
    const int pc = blockIdx.x, tid = threadIdx.x;
    double s = 0.0, q = 0.0;
    for (int c = tid; c < 1024; c += 256) {
        s += (double)part[(size_t)c*256 + pc*2];
        q += (double)part[(size_t)c*256 + pc*2 + 1];
    }
    ssum[tid] = s; ssq[tid] = q; __syncthreads();
    for (int st = 128; st > 0; st >>= 1) {
        if (tid < st) { ssum[tid] += ssum[tid+st]; ssq[tid] += ssq[tid+st]; }
        __syncthreads();
    }
    if (tid == 0) {
        double n   = 2.0 * SPAT;
        double mu  = ssum[0] / n;
        double var = ssq[0] / n - mu*mu;
        double inv = 1.0 / sqrt(var + 1e-5);
        float gg = g_all[j*128 + pc];
        float bb = beta_all[j*128 + pc];
        scale6[j*128 + pc] = (float)(gg * inv);
        shift6[j*128 + pc] = bb - (float)(mu * gg * inv);
    }
}

// ---------------- elementwise normalize + leaky relu (V only) --------------------
__global__ void __launch_bounds__(256) norm_kernel(float* __restrict__ Y,
                                                   const float* __restrict__ scale,
                                                   const float* __restrict__ shift)
{
    int i = blockIdx.x * blockDim.x + threadIdx.x;
    int ch = ((i*4) >> 16) & 127;
    float sc = scale[ch], sh = shift[ch];
    float4 v = *(float4*)(Y + (size_t)i*4);
    float a0 = v.x*sc + sh, a1 = v.y*sc + sh, a2 = v.z*sc + sh, a3 = v.w*sc + sh;
    v.x = fmaxf(a0, 0.01f*a0); v.y = fmaxf(a1, 0.01f*a1);
    v.z = fmaxf(a2, 0.01f*a2); v.w = fmaxf(a3, 0.01f*a3);
    *(float4*)(Y + (size_t)i*4) = v;
}

// ---------------- freq-branch convert: norm+leaky+split, NO transpose ------------
__global__ void __launch_bounds__(256) convert_noT_kernel(const float* __restrict__ Y,
                                                          __nv_bfloat16* __restrict__ hi,
                                                          __nv_bfloat16* __restrict__ lo,
                                                          const float* __restrict__ sc6,
                                                          const float* __restrict__ sh6,
                                                          int j)
{
    const int plane = blockIdx.y;                 // b*128 + p*64 + c
    const int pc = plane & 127;
    const float sc = sc6[j*128 + pc], sh = sh6[j*128 + pc];
    const int b = plane >> 7, p = (plane >> 6) & 1, c = plane & 63;
    const int bp = b*2 + p;
    const int e0 = (blockIdx.x*256 + threadIdx.x) * 8;
    const int f = e0 >> 8, t = e0 & 255;

    const float* ip = Y + (size_t)plane*SPAT + e0;
    float4 v0 = *(const float4*)ip;
    float4 v1 = *(const float4*)(ip + 4);
    float v[8] = {v0.x,v0.y,v0.z,v0.w,v1.x,v1.y,v1.z,v1.w};
    uint32_t wh[4], wl[4];
    #pragma unroll
    for (int u = 0; u < 4; u++) {
        float a = v[2*u]*sc + sh;   a = fmaxf(a, 0.01f*a);
        float bvv = v[2*u+1]*sc + sh; bvv = fmaxf(bvv, 0.01f*bvv);
        wh[u] = pack2(a, bvv);
        wl[u] = pack2(a - bf_hi(a), bvv - bf_hi(bvv));
    }
    size_t ob = ((size_t)(bp*256 + f))*16384 + c*256 + t;
    *(uint4*)(hi + ob) = make_uint4(wh[0],wh[1],wh[2],wh[3]);
    *(uint4*)(lo + ob) = make_uint4(wl[0],wl[1],wl[2],wl[3]);
}

// ---------------- time-branch convert: norm+leaky+split + f/t transpose ----------
__global__ void __launch_bounds__(256) convert_T_kernel(const float* __restrict__ Y,
                                                        __nv_bfloat16* __restrict__ hi,
                                                        __nv_bfloat16* __restrict__ lo,
                                                        const float* __restrict__ sc6,
                                                        const float* __restrict__ sh6,
                                                        int j)
{
    __shared__ float smt[32][33];
    const int plane = blockIdx.z;
    const int pc = plane & 127;
    const float sc = sc6[j*128 + pc], sh = sh6[j*128 + pc];
    const int f0 = blockIdx.x*32, t0 = blockIdx.y*32;
    const int tid = threadIdx.x;
    const int tx = tid & 31, ty = tid >> 5;       // ty 0..7
    const float* ip = Y + (size_t)plane*SPAT;
    #pragma unroll
    for (int jj = 0; jj < 4; jj++) {
        float v = ip[(size_t)(f0 + ty + 8*jj)*256 + t0 + tx];
        v = v*sc + sh;
        v = fmaxf(v, 0.01f*v);
        smt[ty + 8*jj][tx] = v;
    }
    __syncthreads();
    const int b = plane >> 7, p = (plane >> 6) & 1, c = plane & 63;
    const int bp = b*2 + p;
    const int half = tid >> 7;     // 0 = hi, 1 = lo
    const int idx  = tid & 127;
    const int tt = idx >> 2, fg = idx & 3;
    float v[8];
    #pragma unroll
    for (int u = 0; u < 8; u++) v[u] = smt[fg*8 + u][tt];
    size_t ob = ((size_t)(bp*256 + t0 + tt))*16384 + c*256 + f0 + fg*8;
    if (half == 0) {
        uint32_t w[4];
        #pragma unroll
        for (int u = 0; u < 4; u++) w[u] = pack2(v[2*u], v[2*u+1]);
        *(uint4*)(hi + ob) = make_uint4(w[0],w[1],w[2],w[3]);
    } else {
        uint32_t w[4];
        #pragma unroll
        for (int u = 0; u < 4; u++)
            w[u] = pack2(v[2*u] - bf_hi(v[2*u]), v[2*u+1] - bf_hi(v[2*u+1]));
        *(uint4*)(lo + ob) = make_uint4(w[0],w[1],w[2],w[3]);
    }
}

// ---------------- mma.sync score kernel -----------------------------------------
__global__ void __launch_bounds__(256) score_mma_kernel(
    const __nv_bfloat16* __restrict__ khi_, const __nv_bfloat16* __restrict__ klo_,
    const __nv_bfloat16* __restrict__ qhi_, const __nv_bfloat16* __restrict__ qlo_,
    float* __restrict__ srp, float* __restrict__ sip)
{
    extern __shared__ char smc[];
    const uint32_t smem_base = (uint32_t)__cvta_generic_to_shared(smc);
    const int tid = threadIdx.x, wid = tid >> 5, lane = tid & 31;
    const int m0 = blockIdx.x * 128, n0 = blockIdx.y * 128;
    const int b = blockIdx.z >> 5, sl = blockIdx.z & 31;
    const int warp_m = (wid >> 1) * 32, warp_n = (wid & 1) * 64;

    const size_t PL = (size_t)256 * 16384;
    const __nv_bfloat16* srcs[8] = {
        khi_ + (size_t)(b*2+0)*PL + (size_t)m0*16384,
        klo_ + (size_t)(b*2+0)*PL + (size_t)m0*16384,
        khi_ + (size_t)(b*2+1)*PL + (size_t)m0*16384,
        klo_ + (size_t)(b*2+1)*PL + (size_t)m0*16384,
        qhi_ + (size_t)(b*2+0)*PL + (size_t)n0*16384,
        qlo_ + (size_t)(b*2+0)*PL + (size_t)n0*16384,
        qhi_ + (size_t)(b*2+1)*PL + (size_t)n0*16384,
        qlo_ + (size_t)(b*2+1)*PL + (size_t)n0*16384
    };

    float acc[2][2][8][4];
    #pragma unroll
    for (int p = 0; p < 2; p++)
        #pragma unroll
        for (int fm = 0; fm < 2; fm++)
            #pragma unroll
            for (int fn = 0; fn < 8; fn++)
                #pragma unroll
                for (int u = 0; u < 4; u++) acc[p][fm][fn][u] = 0.f;

    const int a_row = (lane & 7) + ((lane >> 3) & 1) * 8;
    const int a_uoff = lane >> 4;
    const int b_row = (lane & 7) + ((lane >> 4) << 3);
    const int b_uoff = (lane >> 3) & 1;

    const int kbase = sl * 512;
    for (int ch = 0; ch < 16; ch++) {
        const int k0 = kbase + ch*32;
        __syncthreads();
        #pragma unroll
        for (int i = 0; i < 16; i++) {
            int idx = tid + i*256;
            int t = idx >> 9, rem = idx & 511;
            int row = rem >> 2, u = rem & 3;
            uint4 v = *(const uint4*)(srcs[t] + (size_t)row*16384 + k0 + u*8);
            *(uint4*)(smc + t*10240 + row*80 + u*16) = v;
        }
        __syncthreads();

        #pragma unroll
        for (int ks = 0; ks < 2; ks++) {
            const int ub = ks*2;
            uint32_t afr[4][2][4];
            #pragma unroll
            for (int t = 0; t < 4; t++)
                #pragma unroll
                for (int fm = 0; fm < 2; fm++) {
                    uint32_t addr = smem_base + t*10240
                                  + (warp_m + fm*16 + a_row)*80 + (ub + a_uoff)*16;
                    ldm4(afr[t][fm], addr);
                }
            uint32_t nKI[2][2][4];
            #pragma unroll
            for (int hl = 0; hl < 2; hl++)
                #pragma unroll
                for (int fm = 0; fm < 2; fm++)
                    #pragma unroll
                    for (int u = 0; u < 4; u++)
                        nKI[hl][fm][u] = afr[2+hl][fm][u] ^ 0x80008000u;

            #pragma unroll
            for (int qop = 0; qop < 4; qop++) {
                uint32_t bfr[8][2];
                #pragma unroll
                for (int pn = 0; pn < 4; pn++) {
                    uint32_t r[4];
                    uint32_t addr = smem_base + (4+qop)*10240
                                  + (warp_n + pn*16 + b_row)*80 + (ub + b_uoff)*16;
                    ldm4(r, addr);
                    bfr[2*pn+0][0] = r[0]; bfr[2*pn+0][1] = r[1];
                    bfr[2*pn+1][0] = r[2]; bfr[2*pn+1][1] = r[3];
                }
                #pragma unroll
                for (int fm = 0; fm < 2; fm++)
                    #pragma unroll
                    for (int fn = 0; fn < 8; fn++) {
                        uint32_t b0 = bfr[fn][0], b1 = bfr[fn][1];
                        if (qop == 0) {
                            mma16816(acc[0][fm][fn], afr[0][fm], b0, b1);
                            mma16816(acc[0][fm][fn], afr[1][fm], b0, b1);
                            mma16816(acc[1][fm][fn], nKI[0][fm], b0, b1);
                            mma16816(acc[1][fm][fn], nKI[1][fm], b0, b1);
                        } else if (qop == 1) {
                            mma16816(acc[0][fm][fn], afr[0][fm], b0, b1);
                            mma16816(acc[1][fm][fn], nKI[0][fm], b0, b1);
                        } else if (qop == 2) {
                            mma16816(acc[0][fm][fn], afr[2][fm], b0, b1);
                            mma16816(acc[0][fm][fn], afr[3][fm], b0, b1);
                            mma16816(acc[1][fm][fn], afr[0][fm], b0, b1);
                            mma16816(acc[1][fm][fn], afr[1][fm], b0, b1);
                        } else {
                            mma16816(acc[0][fm][fn], afr[2][fm], b0, b1);
                            mma16816(acc[1][fm][fn], afr[0][fm], b0, b1);
                        }
                    }
            }
        }
    }

    const int rl = lane >> 2, cl = (lane & 3) * 2;
    #pragma unroll
    for (int fm = 0; fm < 2; fm++)
        #pragma unroll
        for (int fn = 0; fn < 8; fn++) {
            int m = m0 + warp_m + fm*16 + rl;
            int n = n0 + warp_n + fn*8 + cl;
            size_t off = (((size_t)sl*2 + b)*256 + m)*256 + n;
            float* c0 = acc[0][fm][fn];
            float* c1 = acc[1][fm][fn];
            *(float2*)(srp + off)         = make_float2(c0[0], c0[1]);
            *(float2*)(srp + off + 8*256) = make_float2(c0[2], c0[3]);
            *(float2*)(sip + off)         = make_float2(c1[0], c1[1]);
            *(float2*)(sip + off + 8*256) = make_float2(c1[2], c1[3]);
        }
}

// ---------------- softmax over query axis n --------------------------------------
__global__ void __launch_bounds__(256) softmax_kernel(const float* __restrict__ srp,
                                                      const float* __restrict__ sip,
                                                      float* __restrict__ A)
{
    __shared__ float red[256];
    const int bm = blockIdx.x;
    const int b = bm >> 8, m = bm & 255;
    const int n = threadIdx.x;
    float sr = 0.f, si = 0.f;
    for (int sl = 0; sl < KSLICES; sl++) {
        size_t off = (((size_t)sl*2 + b)*256 + m)*256 + n;
        sr += srp[off]; si += sip[off];
    }
    float z = sqrtf(sr*sr + si*si);
    red[n] = z; __syncthreads();
    for (int st = 128; st > 0; st >>= 1) {
        if (n < st) red[n] = fmaxf(red[n], red[n+st]);
        __syncthreads();
    }
    float mx = red[0]; __syncthreads();
    float e = expf(z - mx);
    red[n] = e; __syncthreads();
    for (int st = 128; st > 0; st >>= 1) {
        if (n < st) red[n] += red[n+st];
        __syncthreads();
    }
    A[((size_t)b*256 + m)*256 + n] = e / red[0];
}

// ---------------- time-branch output ---------------------------------------------
__global__ void __launch_bounds__(256) out_time_kernel(const float* __restrict__ V,
                                                       const float* __restrict__ A,
                                                       float* __restrict__ out)
{
    __shared__ float Vs[32*132];
    __shared__ float As[32*128];
    const int r0 = blockIdx.x*128, n0 = blockIdx.y*128, b = blockIdx.z;
    const int tid = threadIdx.x, tx = tid & 15, ty = tid >> 4;
    float acc[8][8];
    #pragma unroll
    for (int i = 0; i < 8; i++)
        #pragma unroll
        for (int q = 0; q < 8; q++) acc[i][q] = 0.f;

    for (int c = 0; c < 8; c++) {
        __syncthreads();
        const int m0c = c*32;
        #pragma unroll
        for (int u = 0; u < 4; u++) {
            int idx4 = tid + u*256;
            int kk   = idx4 >> 5;
            int col4 = (idx4 & 31) << 2;
            *(float4*)(As + kk*128 + col4) =
                *(const float4*)(A + ((size_t)b*256 + m0c + kk)*256 + n0 + col4);
            int mg  = idx4 & 7;
            int row = idx4 >> 3;
            float4 v = *(const float4*)(V + (size_t)(b*32768 + r0 + row)*256 + m0c + mg*4);
            Vs[(mg*4+0)*132 + row] = v.x;
            Vs[(mg*4+1)*132 + row] = v.y;
            Vs[(mg*4+2)*132 + row] = v.z;
            Vs[(mg*4+3)*132 + row] = v.w;
        }
        __syncthreads();
        #pragma unroll 4
        for (int kk = 0; kk < 32; kk++) {
            float4 v0 = *(const float4*)(Vs + kk*132 + ty*4);
            float4 v1 = *(const float4*)(Vs + kk*132 + 64 + ty*4);
            float4 a0 = *(const float4*)(As + kk*128 + tx*4);
            float4 a1 = *(const float4*)(As + kk*128 + 64 + tx*4);
            float vv[8] = {v0.x,v0.y,v0.z,v0.w,v1.x,v1.y,v1.z,v1.w};
            float av[8] = {a0.x,a0.y,a0.z,a0.w,a1.x,a1.y,a1.z,a1.w};
            #pragma unroll
            for (int i = 0; i < 8; i++)
                #pragma unroll
                for (int q = 0; q < 8; q++) acc[i][q] += vv[i]*av[q];
        }
    }
    #pragma unroll
    for (int i = 0; i < 8; i++) {
        int r = (i < 4) ? (r0 + ty*4 + i) : (r0 + 64 + ty*4 + (i-4));
        float* dst = out + (size_t)(b*32768 + r)*256 + n0;
        *(float4*)(dst + tx*4)      = make_float4(acc[i][0],acc[i][1],acc[i][2],acc[i][3]);
        *(float4*)(dst + 64 + tx*4) = make_float4(acc[i][4],acc[i][5],acc[i][6],acc[i][7]);
    }
}

// ---------------- freq-branch output ---------------------------------------------
__global__ void __launch_bounds__(256) out_freq_kernel(const float* __restrict__ V,
                                                       const float* __restrict__ A,
                                                       float* __restrict__ out)
{
    __shared__ float As[32*128];
    __shared__ float Vs[32*128];
    const int f0 = (blockIdx.x >> 1)*128, t0 = (blockIdx.x & 1)*128;
    const int plane = blockIdx.y;
    const int b = plane >> 7;
    const size_t vbase = (size_t)plane * SPAT;
    const int tid = threadIdx.x, tx = tid & 15, ty = tid >> 4;
    float acc[8][8];
    #pragma unroll
    for (int i = 0; i < 8; i++)
        #pragma unroll
        for (int q = 0; q < 8; q++) acc[i][q] = 0.f;

    for (int c = 0; c < 8; c++) {
        __syncthreads();
        const int m0c = c*32;
        #pragma unroll
        for (int u = 0; u < 4; u++) {
            int idx4 = tid + u*256;
            int kk   = idx4 >> 5;
            int col4 = (idx4 & 31) << 2;
            *(float4*)(As + kk*128 + col4) =
                *(const float4*)(A + ((size_t)b*256 + m0c + kk)*256 + f0 + col4);
            *(float4*)(Vs + kk*128 + col4) =
                *(const float4*)(V + vbase + (size_t)(m0c + kk)*256 + t0 + col4);
        }
        __syncthreads();
        #pragma unroll 4
        for (int kk = 0; kk < 32; kk++) {
            float4 a0 = *(const float4*)(As + kk*128 + ty*4);
            float4 a1 = *(const float4*)(As + kk*128 + 64 + ty*4);
            float4 v0 = *(const float4*)(Vs + kk*128 + tx*4);
            float4 v1 = *(const float4*)(Vs + kk*128 + 64 + tx*4);
            float av[8] = {a0.x,a0.y,a0.z,a0.w,a1.x,a1.y,a1.z,a1.w};
            float vv[8] = {v0.x,v0.y,v0.z,v0.w,v1.x,v1.y,v1.z,v1.w};
            #pragma unroll
            for (int i = 0; i < 8; i++)
                #pragma unroll
                for (int q = 0; q < 8; q++) acc[i][q] += av[i]*vv[q];
        }
    }
    #pragma unroll
    for (int i = 0; i < 8; i++) {
        int f = (i < 4) ? (f0 + ty*4 + i) : (f0 + 64 + ty*4 + (i-4));
        float* dst = out + vbase + (size_t)f*256 + t0;
        float4 o0 = *(float4*)(dst + tx*4);
        float4 o1 = *(float4*)(dst + 64 + tx*4);
        o0.x += acc[i][0]; o0.y += acc[i][1]; o0.z += acc[i][2]; o0.w += acc[i][3];
        o1.x += acc[i][4]; o1.y += acc[i][5]; o1.z += acc[i][6]; o1.w += acc[i][7];
        *(float4*)(dst + tx*4)      = o0;
        *(float4*)(dst + 64 + tx*4) = o1;
    }
}

// ---------------- host launch ----------------------------------------------------
extern "C" void kernel_launch(void* const* d_in, const int* in_sizes, int n_in,
                              void* d_out, int out_size)
{
    const float* P    = (const float*)d_in[0];
    const float* Q    = (const float*)d_in[1];
    const float* W    = (const float*)d_in[2];
    // d_in[3] = bias: cancels exactly under BN mean subtraction -> unused
    const float* g    = (const float*)d_in[4];
    const float* beta = (const float*)d_in[5];
    float* out = (float*)d_out;

    float *qp, *kp, *vp, *srp, *sip, *ap, *scp, *shp, *partp;
    __nv_bfloat16 *qhi, *qlo, *khi, *klo, *pshi, *pslo, *qshi, *qslo, *wcp;
    cudaGetSymbolAddress((void**)&qp,  g_q);
    cudaGetSymbolAddress((void**)&kp,  g_k);
    cudaGetSymbolAddress((void**)&vp,  g_v);
    cudaGetSymbolAddress((void**)&qhi, g_qhi);
    cudaGetSymbolAddress((void**)&qlo, g_qlo);
    cudaGetSymbolAddress((void**)&khi, g_khi);
    cudaGetSymbolAddress((void**)&klo, g_klo);
    cudaGetSymbolAddress((void**)&pshi, g_pshi);
    cudaGetSymbolAddress((void**)&pslo, g_pslo);
    cudaGetSymbolAddress((void**)&qshi, g_qshi);
    cudaGetSymbolAddress((void**)&qslo, g_qslo);
    cudaGetSymbolAddress((void**)&wcp, g_wc);
    cudaGetSymbolAddress((void**)&partp, g_part);
    cudaGetSymbolAddress((void**)&srp, g_srp);
    cudaGetSymbolAddress((void**)&sip, g_sip);
    cudaGetSymbolAddress((void**)&ap,  g_a);
    cudaGetSymbolAddress((void**)&scp, g_scale6);
    cudaGetSymbolAddress((void**)&shp, g_shift6);

    cudaFuncSetAttribute(conv_mma_kernel, cudaFuncAttributeMaxDynamicSharedMemorySize, CONV2_SMEM);
    cudaFuncSetAttribute(score_mma_kernel, cudaFuncAttributeMaxDynamicSharedMemorySize, SC2_SMEM);

    // one-time prep
    split_kernel<<<16384, 256>>>(P, pshi, pslo);
    split_kernel<<<16384, 256>>>(Q, qshi, qslo);
    wcomb_kernel<<<dim3(64, 6), 256>>>(W, wcp);

    auto conv_stats = [&](const __nv_bfloat16* xhi, const __nv_bfloat16* xlo,
                          int j, float* Y) {
        conv_mma_kernel<<<dim3(512, 2), 256, CONV2_SMEM>>>(xhi, xlo, wcp + (size_t)j*32768, Y, partp);
        stats_reduce_kernel<<<128, 256>>>(partp, g, beta, j, scp, shp);
    };

    // ---- time branch ----
    conv_stats(qshi, qslo, 0, qp);
    convert_T_kernel<<<dim3(8, 8, 256), 256>>>(qp, qhi, qlo, scp, shp, 0);
    conv_stats(pshi, pslo, 1, kp);
    convert_T_kernel<<<dim3(8, 8, 256), 256>>>(kp, khi, klo, scp, shp, 1);
    conv_stats(pshi, pslo, 2, vp);
    norm_kernel<<<16384, 256>>>(vp, scp + 2*128, shp + 2*128);
    score_mma_kernel<<<dim3(2, 2, 64), 256, SC2_SMEM>>>(khi, klo, qhi, qlo, srp, sip);
    softmax_kernel<<<512, 256>>>(srp, sip, ap);
    out_time_kernel<<<dim3(256, 2, 2), 256>>>(vp, ap, out);

    // ---- freq branch ----
    conv_stats(qshi, qslo, 3, qp);
    convert_noT_kernel<<<dim3(32, 256), 256>>>(qp, qhi, qlo, scp, shp, 3);
    conv_stats(pshi, pslo, 4, kp);
    convert_noT_kernel<<<dim3(32, 256), 256>>>(kp, khi, klo, scp, shp, 4);
    conv_stats(pshi, pslo, 5, vp);
    norm_kernel<<<16384, 256>>>(vp, scp + 5*128, shp + 5*128);
    score_mma_kernel<<<dim3(2, 2, 64), 256, SC2_SMEM>>>(khi, klo, qhi, qlo, srp, sip);
    softmax_kernel<<<512, 256>>>(srp, sip, ap);
    out_freq_kernel<<<dim3(4, 256), 256>>>(vp, ap, out);
}

// round 7
// speedup vs baseline: 2.9344x; 1.3390x over previous
#include <cuda_runtime.h>
#include <cuda_bf16.h>
#include <math.h>
#include <stdint.h>

#define SPAT 65536      // F*T = 256*256
#define KSLICES 32
#define CONV2_SMEM (2*34816 + 2*17408)       // A hi/lo + double-buffered B = 104448
#define SC2_SMEM   (8*128*80)                // 81920 bytes

// ---------------- scratch (device globals; no allocation allowed) ----------------
__device__ float g_q[16777216];
__device__ float g_k[16777216];
__device__ float g_v[16777216];
__device__ __nv_bfloat16 g_qhi[16777216];    // score operands [bp:4][row:256][k:16384]
__device__ __nv_bfloat16 g_qlo[16777216];
__device__ __nv_bfloat16 g_khi[16777216];
__device__ __nv_bfloat16 g_klo[16777216];
__device__ __nv_bfloat16 g_vhi[16777216];    // normalized V bf16 hi/lo
__device__ __nv_bfloat16 g_vlo[16777216];
__device__ __nv_bfloat16 g_pshi[16777216];   // split inputs P
__device__ __nv_bfloat16 g_pslo[16777216];
__device__ __nv_bfloat16 g_qshi[16777216];   // split inputs Q
__device__ __nv_bfloat16 g_qslo[16777216];
__device__ __nv_bfloat16 g_ahi[2*256*256];   // softmax hi/lo [b][m][n]
__device__ __nv_bfloat16 g_alo[2*256*256];
__device__ __nv_bfloat16 g_wc[6*2*16384];    // combined weights [j][hl][o][cc]
__device__ float g_part[1024*256];           // conv stats partials
__device__ float g_srp[KSLICES*2*256*256];   // partial sr [slice][b][m][n]
__device__ float g_sip[KSLICES*2*256*256];
__device__ float g_scale6[6*128];
__device__ float g_shift6[6*128];

// ================= mma.sync / cp.async helpers ===================================
__device__ __forceinline__ void ldm4(uint32_t* r, uint32_t addr) {
    asm volatile("ldmatrix.sync.aligned.m8n8.x4.shared.b16 {%0,%1,%2,%3}, [%4];"
                 : "=r"(r[0]), "=r"(r[1]), "=r"(r[2]), "=r"(r[3]) : "r"(addr));
}
__device__ __forceinline__ void ldm4t(uint32_t* r, uint32_t addr) {
    asm volatile("ldmatrix.sync.aligned.m8n8.x4.trans.shared.b16 {%0,%1,%2,%3}, [%4];"
                 : "=r"(r[0]), "=r"(r[1]), "=r"(r[2]), "=r"(r[3]) : "r"(addr));
}
__device__ __forceinline__ void mma16816(float* c, const uint32_t* a,
                                         uint32_t b0, uint32_t b1) {
    asm volatile(
        "mma.sync.aligned.m16n8k16.row.col.f32.bf16.bf16.f32 "
        "{%0,%1,%2,%3}, {%4,%5,%6,%7}, {%8,%9}, {%0,%1,%2,%3};"
        : "+f"(c[0]), "+f"(c[1]), "+f"(c[2]), "+f"(c[3])
        : "r"(a[0]), "r"(a[1]), "r"(a[2]), "r"(a[3]), "r"(b0), "r"(b1));
}
#define CPA16(sa, gp)  asm volatile("cp.async.cg.shared.global [%0], [%1], 16;" :: "r"(sa), "l"(gp))
#define CPA_COMMIT()   asm volatile("cp.async.commit_group;" ::: "memory")
#define CPA_WAIT(n)    asm volatile("cp.async.wait_group %0;" :: "n"(n) : "memory")

// ---------------- helpers for bf16 split ----------------------------------------
__device__ __forceinline__ uint32_t pack2(float a, float b) {
    __nv_bfloat16 ha = __float2bfloat16_rn(a);
    __nv_bfloat16 hb = __float2bfloat16_rn(b);
    return (uint32_t)__bfloat16_as_ushort(ha) | ((uint32_t)__bfloat16_as_ushort(hb) << 16);
}
__device__ __forceinline__ float bf_hi(float v) {
    return __bfloat162float(__float2bfloat16_rn(v));
}

// ---------------- split input fp32 -> bf16 hi/lo ---------------------------------
__global__ void __launch_bounds__(256) split_kernel(const float* __restrict__ X,
                                                    __nv_bfloat16* __restrict__ hi,
                                                    __nv_bfloat16* __restrict__ lo)
{
    size_t i = ((size_t)blockIdx.x*256 + threadIdx.x) * 4;
    float4 v = *(const float4*)(X + i);
    uint2 h, l;
    h.x = pack2(v.x, v.y); h.y = pack2(v.z, v.w);
    l.x = pack2(v.x - bf_hi(v.x), v.y - bf_hi(v.y));
    l.y = pack2(v.z - bf_hi(v.z), v.w - bf_hi(v.w));
    *(uint2*)(hi + i) = h;
    *(uint2*)(lo + i) = l;
}

// ---------------- build combined complex weight matrices (bf16 hi/lo) ------------
__global__ void __launch_bounds__(256) wcomb_kernel(const float* __restrict__ W6,
                                                    __nv_bfloat16* __restrict__ wc)
{
    const int j = blockIdx.y;
    const int idx = blockIdx.x*256 + threadIdx.x;
    const int o = idx & 127, cc = idx >> 7;
    const float* Wr = W6 + (size_t)(j*2 + 0)*4096;
    const float* Wi = W6 + (size_t)(j*2 + 1)*4096;
    const int oc = (o & 63)*64 + (cc & 63);
    float val;
    if (o < 64) val = (cc < 64) ?  Wr[oc] : -Wi[oc];
    else        val = (cc < 64) ?  Wi[oc] :  Wr[oc];
    float h = bf_hi(val);
    wc[(size_t)j*32768 + o*128 + cc]         = __float2bfloat16_rn(h);
    wc[(size_t)j*32768 + 16384 + o*128 + cc] = __float2bfloat16_rn(val - h);
}

// ---------------- tensor-core conv with cp.async double-buffered B ---------------
__global__ void __launch_bounds__(256) conv_mma_kernel(
    const __nv_bfloat16* __restrict__ Xhi, const __nv_bfloat16* __restrict__ Xlo,
    const __nv_bfloat16* __restrict__ Wc,
    float* __restrict__ Y, float* __restrict__ part)
{
    extern __shared__ char smb[];
    __shared__ float stats_s[2][128][2];
    const uint32_t sb = (uint32_t)__cvta_generic_to_shared(smb);
    const int tid = threadIdx.x, wid = tid >> 5, lane = tid & 31;
    const int b = blockIdx.y, s0 = blockIdx.x * 128;
    const int warp_m = (wid >> 1) * 32, warp_n = (wid & 1) * 64;
    const int cta = blockIdx.y*512 + blockIdx.x;

    // A smem: [hl][o:128][cc:128] bf16, pitch 272 B
    for (int i = tid; i < 4096; i += 256) {
        int hl = i >> 11, rem = i & 2047;
        int row = rem >> 4, u = rem & 15;
        uint4 v = *(const uint4*)(Wc + hl*16384 + row*128 + u*8);
        *(uint4*)(smb + hl*34816 + row*272 + u*16) = v;
    }

    const __nv_bfloat16* xh = Xhi + (size_t)b*8388608 + s0;
    const __nv_bfloat16* xl = Xlo + (size_t)b*8388608 + s0;

    auto issueB = [&](int c, int d) {
        #pragma unroll
        for (int i = 0; i < 4; i++) {
            int idx = tid + i*256;
            int hl = idx >> 9, rem = idx & 511;
            int kk = rem >> 4, u = rem & 15;
            const __nv_bfloat16* gp = (hl ? xl : xh) + (size_t)(c*32 + kk)*SPAT + u*8;
            CPA16(sb + 69632 + d*17408 + hl*8704 + kk*272 + u*16, gp);
        }
        CPA_COMMIT();
    };

    float acc[2][8][4];
    #pragma unroll
    for (int fm = 0; fm < 2; fm++)
        #pragma unroll
        for (int fn = 0; fn < 8; fn++)
            #pragma unroll
            for (int u = 0; u < 4; u++) acc[fm][fn][u] = 0.f;

    const int a_row = (lane & 7) + ((lane >> 3) & 1) * 8;
    const int a_u   = lane >> 4;
    const int bt_row = (lane & 7) + ((lane >> 3) & 1) * 8;
    const int bt_c   = (lane >> 4) * 8;

    issueB(0, 0);
    #pragma unroll
    for (int c = 0; c < 4; c++) {
        if (c < 3) { issueB(c+1, (c+1) & 1); CPA_WAIT(1); }
        else       { CPA_WAIT(0); }
        __syncthreads();
        const uint32_t bbase = sb + 69632 + (c & 1)*17408;
        #pragma unroll
        for (int ks = 0; ks < 2; ks++) {
            uint32_t Ah[2][4], Al[2][4];
            #pragma unroll
            for (int fm = 0; fm < 2; fm++) {
                uint32_t arow_off = (warp_m + fm*16 + a_row)*272 + c*64 + ks*32 + a_u*16;
                ldm4(Ah[fm], sb + arow_off);
                ldm4(Al[fm], sb + 34816 + arow_off);
            }
            uint32_t Bh[8][2], Bl[8][2];
            #pragma unroll
            for (int fn2 = 0; fn2 < 4; fn2++) {
                uint32_t boff = (ks*16 + bt_row)*272 + (warp_n + fn2*16 + bt_c)*2;
                uint32_t r[4];
                ldm4t(r, bbase + boff);
                Bh[2*fn2+0][0] = r[0]; Bh[2*fn2+0][1] = r[1];
                Bh[2*fn2+1][0] = r[2]; Bh[2*fn2+1][1] = r[3];
                ldm4t(r, bbase + 8704 + boff);
                Bl[2*fn2+0][0] = r[0]; Bl[2*fn2+0][1] = r[1];
                Bl[2*fn2+1][0] = r[2]; Bl[2*fn2+1][1] = r[3];
            }
            #pragma unroll
            for (int fm = 0; fm < 2; fm++)
                #pragma unroll
                for (int fn = 0; fn < 8; fn++) {
                    mma16816(acc[fm][fn], Ah[fm], Bh[fn][0], Bh[fn][1]);
                    mma16816(acc[fm][fn], Ah[fm], Bl[fn][0], Bl[fn][1]);
                    mma16816(acc[fm][fn], Al[fm], Bh[fn][0], Bh[fn][1]);
                }
        }
        __syncthreads();
    }

    // epilogue: write Y + per-channel partial stats
    const int rl = lane >> 2, cl = (lane & 3) * 2;
    float* Yb = Y + (size_t)b*8388608;
    float su[2][2] = {}, sq[2][2] = {};
    #pragma unroll
    for (int fm = 0; fm < 2; fm++) {
        int r = warp_m + fm*16 + rl;
        #pragma unroll
        for (int fn = 0; fn < 8; fn++) {
            float* cc4 = acc[fm][fn];
            int ncol = warp_n + fn*8 + cl;
            *(float2*)(Yb + (size_t)r*SPAT + s0 + ncol)     = make_float2(cc4[0], cc4[1]);
            *(float2*)(Yb + (size_t)(r+8)*SPAT + s0 + ncol) = make_float2(cc4[2], cc4[3]);
            su[fm][0] += cc4[0] + cc4[1];
            sq[fm][0] += cc4[0]*cc4[0] + cc4[1]*cc4[1];
            su[fm][1] += cc4[2] + cc4[3];
            sq[fm][1] += cc4[2]*cc4[2] + cc4[3]*cc4[3];
        }
    }
    #pragma unroll
    for (int d = 1; d < 4; d <<= 1)
        #pragma unroll
        for (int fm = 0; fm < 2; fm++)
            #pragma unroll
            for (int h = 0; h < 2; h++) {
                su[fm][h] += __shfl_xor_sync(0xFFFFFFFF, su[fm][h], d);
                sq[fm][h] += __shfl_xor_sync(0xFFFFFFFF, sq[fm][h], d);
            }
    if ((lane & 3) == 0) {
        #pragma unroll
        for (int fm = 0; fm < 2; fm++)
            #pragma unroll
            for (int h = 0; h < 2; h++) {
                int row = warp_m + fm*16 + rl + h*8;
                stats_s[wid & 1][row][0] = su[fm][h];
                stats_s[wid & 1][row][1] = sq[fm][h];
            }
    }
    __syncthreads();
    {
        int row = tid >> 1, cp = tid & 1;
        part[(size_t)cta*256 + tid] = stats_s[0][row][cp] + stats_s[1][row][cp];
    }
}

// ---------------- reduce conv partials -> BN scale/shift -------------------------
__global__ void __launch_bounds__(256) stats_reduce_kernel(const float* __restrict__ part,
                                                           const float* __restrict__ g_all,
                                                           const float* __restrict__ beta_all,
                                                           int j,
                                                           float* __restrict__ scale6,
                                                           float* __restrict__ shift6)
{
    __shared__ double ssum[256];
    __shared__ double ssq[256];
    const int pc = blockIdx.x, tid = threadIdx.x;
    double s = 0.0, q = 0.0;
    for (int c = tid; c < 1024; c += 256) {
        s += (double)part[(size_t)c*256 + pc*2];
        q += (double)part[(size_t)c*256 + pc*2 + 1];
    }
    ssum[tid] = s; ssq[tid] = q; __syncthreads();
    for (int st = 128; st > 0; st >>= 1) {
        if (tid < st) { ssum[tid] += ssum[tid+st]; ssq[tid] += ssq[tid+st]; }
        __syncthreads();
    }
    if (tid == 0) {
        double n   = 2.0 * SPAT;
        double mu  = ssum[0] / n;
        double var = ssq[0] / n - mu*mu;
        double inv = 1.0 / sqrt(var + 1e-5);
        float gg = g_all[j*128 + pc];
        float bb = beta_all[j*128 + pc];
        scale6[j*128 + pc] = (float)(gg * inv);
        shift6[j*128 + pc] = bb - (float)(mu * gg * inv);
    }
}

// ---------------- V convert: norm + leaky + bf16 split ---------------------------
__global__ void __launch_bounds__(256) vconvert_kernel(const float* __restrict__ Y,
                                                       __nv_bfloat16* __restrict__ hi,
                                                       __nv_bfloat16* __restrict__ lo,
                                                       const float* __restrict__ sc6,
                                                       const float* __restrict__ sh6,
                                                       int j)
{
    size_t i = ((size_t)blockIdx.x*256 + threadIdx.x) * 4;
    int ch = (int)((i >> 16) & 127);
    float sc = sc6[j*128 + ch], sh = sh6[j*128 + ch];
    float4 v = *(const float4*)(Y + i);
    float a0 = v.x*sc + sh, a1 = v.y*sc + sh, a2 = v.z*sc + sh, a3 = v.w*sc + sh;
    a0 = fmaxf(a0, 0.01f*a0); a1 = fmaxf(a1, 0.01f*a1);
    a2 = fmaxf(a2, 0.01f*a2); a3 = fmaxf(a3, 0.01f*a3);
    uint2 h, l;
    h.x = pack2(a0, a1); h.y = pack2(a2, a3);
    l.x = pack2(a0 - bf_hi(a0), a1 - bf_hi(a1));
    l.y = pack2(a2 - bf_hi(a2), a3 - bf_hi(a3));
    *(uint2*)(hi + i) = h;
    *(uint2*)(lo + i) = l;
}

// ---------------- freq-branch convert: norm+leaky+split, NO transpose ------------
__global__ void __launch_bounds__(256) convert_noT_kernel(const float* __restrict__ Y,
                                                          __nv_bfloat16* __restrict__ hi,
                                                          __nv_bfloat16* __restrict__ lo,
                                                          const float* __restrict__ sc6,
                                                          const float* __restrict__ sh6,
                                                          int j)
{
    const int plane = blockIdx.y;
    const int pc = plane & 127;
    const float sc = sc6[j*128 + pc], sh = sh6[j*128 + pc];
    const int b = plane >> 7, p = (plane >> 6) & 1, c = plane & 63;
    const int bp = b*2 + p;
    const int e0 = (blockIdx.x*256 + threadIdx.x) * 8;
    const int f = e0 >> 8, t = e0 & 255;

    const float* ip = Y + (size_t)plane*SPAT + e0;
    float4 v0 = *(const float4*)ip;
    float4 v1 = *(const float4*)(ip + 4);
    float v[8] = {v0.x,v0.y,v0.z,v0.w,v1.x,v1.y,v1.z,v1.w};
    uint32_t wh[4], wl[4];
    #pragma unroll
    for (int u = 0; u < 4; u++) {
        float a = v[2*u]*sc + sh;   a = fmaxf(a, 0.01f*a);
        float bvv = v[2*u+1]*sc + sh; bvv = fmaxf(bvv, 0.01f*bvv);
        wh[u] = pack2(a, bvv);
        wl[u] = pack2(a - bf_hi(a), bvv - bf_hi(bvv));
    }
    size_t ob = ((size_t)(bp*256 + f))*16384 + c*256 + t;
    *(uint4*)(hi + ob) = make_uint4(wh[0],wh[1],wh[2],wh[3]);
    *(uint4*)(lo + ob) = make_uint4(wl[0],wl[1],wl[2],wl[3]);
}

// ---------------- time-branch convert: norm+leaky+split + f/t transpose ----------
__global__ void __launch_bounds__(256) convert_T_kernel(const float* __restrict__ Y,
                                                        __nv_bfloat16* __restrict__ hi,
                                                        __nv_bfloat16* __restrict__ lo,
                                                        const float* __restrict__ sc6,
                                                        const float* __restrict__ sh6,
                                                        int j)
{
    __shared__ float smt[32][33];
    const int plane = blockIdx.z;
    const int pc = plane & 127;
    const float sc = sc6[j*128 + pc], sh = sh6[j*128 + pc];
    const int f0 = blockIdx.x*32, t0 = blockIdx.y*32;
    const int tid = threadIdx.x;
    const int tx = tid & 31, ty = tid >> 5;
    const float* ip = Y + (size_t)plane*SPAT;
    #pragma unroll
    for (int jj = 0; jj < 4; jj++) {
        float v = ip[(size_t)(f0 + ty + 8*jj)*256 + t0 + tx];
        v = v*sc + sh;
        v = fmaxf(v, 0.01f*v);
        smt[ty + 8*jj][tx] = v;
    }
    __syncthreads();
    const int b = plane >> 7, p = (plane >> 6) & 1, c = plane & 63;
    const int bp = b*2 + p;
    const int half = tid >> 7;
    const int idx  = tid & 127;
    const int tt = idx >> 2, fg = idx & 3;
    float v[8];
    #pragma unroll
    for (int u = 0; u < 8; u++) v[u] = smt[fg*8 + u][tt];
    size_t ob = ((size_t)(bp*256 + t0 + tt))*16384 + c*256 + f0 + fg*8;
    if (half == 0) {
        uint32_t w[4];
        #pragma unroll
        for (int u = 0; u < 4; u++) w[u] = pack2(v[2*u], v[2*u+1]);
        *(uint4*)(hi + ob) = make_uint4(w[0],w[1],w[2],w[3]);
    } else {
        uint32_t w[4];
        #pragma unroll
        for (int u = 0; u < 4; u++)
            w[u] = pack2(v[2*u] - bf_hi(v[2*u]), v[2*u+1] - bf_hi(v[2*u+1]));
        *(uint4*)(lo + ob) = make_uint4(w[0],w[1],w[2],w[3]);
    }
}

// ---------------- mma.sync score kernel -----------------------------------------
__global__ void __launch_bounds__(256) score_mma_kernel(
    const __nv_bfloat16* __restrict__ khi_, const __nv_bfloat16* __restrict__ klo_,
    const __nv_bfloat16* __restrict__ qhi_, const __nv_bfloat16* __restrict__ qlo_,
    float* __restrict__ srp, float* __restrict__ sip)
{
    extern __shared__ char smc[];
    const uint32_t smem_base = (uint32_t)__cvta_generic_to_shared(smc);
    const int tid = threadIdx.x, wid = tid >> 5, lane = tid & 31;
    const int m0 = blockIdx.x * 128, n0 = blockIdx.y * 128;
    const int b = blockIdx.z >> 5, sl = blockIdx.z & 31;
    const int warp_m = (wid >> 1) * 32, warp_n = (wid & 1) * 64;

    const size_t PL = (size_t)256 * 16384;
    const __nv_bfloat16* srcs[8] = {
        khi_ + (size_t)(b*2+0)*PL + (size_t)m0*16384,
        klo_ + (size_t)(b*2+0)*PL + (size_t)m0*16384,
        khi_ + (size_t)(b*2+1)*PL + (size_t)m0*16384,
        klo_ + (size_t)(b*2+1)*PL + (size_t)m0*16384,
        qhi_ + (size_t)(b*2+0)*PL + (size_t)n0*16384,
        qlo_ + (size_t)(b*2+0)*PL + (size_t)n0*16384,
        qhi_ + (size_t)(b*2+1)*PL + (size_t)n0*16384,
        qlo_ + (size_t)(b*2+1)*PL + (size_t)n0*16384
    };

    float acc[2][2][8][4];
    #pragma unroll
    for (int p = 0; p < 2; p++)
        #pragma unroll
        for (int fm = 0; fm < 2; fm++)
            #pragma unroll
            for (int fn = 0; fn < 8; fn++)
                #pragma unroll
                for (int u = 0; u < 4; u++) acc[p][fm][fn][u] = 0.f;

    const int a_row = (lane & 7) + ((lane >> 3) & 1) * 8;
    const int a_uoff = lane >> 4;
    const int b_row = (lane & 7) + ((lane >> 4) << 3);
    const int b_uoff = (lane >> 3) & 1;

    const int kbase = sl * 512;
    for (int ch = 0; ch < 16; ch++) {
        const int k0 = kbase + ch*32;
        __syncthreads();
        #pragma unroll
        for (int i = 0; i < 16; i++) {
            int idx = tid + i*256;
            int t = idx >> 9, rem = idx & 511;
            int row = rem >> 2, u = rem & 3;
            uint4 v = *(const uint4*)(srcs[t] + (size_t)row*16384 + k0 + u*8);
            *(uint4*)(smc + t*10240 + row*80 + u*16) = v;
        }
        __syncthreads();

        #pragma unroll
        for (int ks = 0; ks < 2; ks++) {
            const int ub = ks*2;
            uint32_t afr[4][2][4];
            #pragma unroll
            for (int t = 0; t < 4; t++)
                #pragma unroll
                for (int fm = 0; fm < 2; fm++) {
                    uint32_t addr = smem_base + t*10240
                                  + (warp_m + fm*16 + a_row)*80 + (ub + a_uoff)*16;
                    ldm4(afr[t][fm], addr);
                }
            uint32_t nKI[2][2][4];
            #pragma unroll
            for (int hl = 0; hl < 2; hl++)
                #pragma unroll
                for (int fm = 0; fm < 2; fm++)
                    #pragma unroll
                    for (int u = 0; u < 4; u++)
                        nKI[hl][fm][u] = afr[2+hl][fm][u] ^ 0x80008000u;

            #pragma unroll
            for (int qop = 0; qop < 4; qop++) {
                uint32_t bfr[8][2];
                #pragma unroll
                for (int pn = 0; pn < 4; pn++) {
                    uint32_t r[4];
                    uint32_t addr = smem_base + (4+qop)*10240
                                  + (warp_n + pn*16 + b_row)*80 + (ub + b_uoff)*16;
                    ldm4(r, addr);
                    bfr[2*pn+0][0] = r[0]; bfr[2*pn+0][1] = r[1];
                    bfr[2*pn+1][0] = r[2]; bfr[2*pn+1][1] = r[3];
                }
                #pragma unroll
                for (int fm = 0; fm < 2; fm++)
                    #pragma unroll
                    for (int fn = 0; fn < 8; fn++) {
                        uint32_t b0 = bfr[fn][0], b1 = bfr[fn][1];
                        if (qop == 0) {
                            mma16816(acc[0][fm][fn], afr[0][fm], b0, b1);
                            mma16816(acc[0][fm][fn], afr[1][fm], b0, b1);
                            mma16816(acc[1][fm][fn], nKI[0][fm], b0, b1);
                            mma16816(acc[1][fm][fn], nKI[1][fm], b0, b1);
                        } else if (qop == 1) {
                            mma16816(acc[0][fm][fn], afr[0][fm], b0, b1);
                            mma16816(acc[1][fm][fn], nKI[0][fm], b0, b1);
                        } else if (qop == 2) {
                            mma16816(acc[0][fm][fn], afr[2][fm], b0, b1);
                            mma16816(acc[0][fm][fn], afr[3][fm], b0, b1);
                            mma16816(acc[1][fm][fn], afr[0][fm], b0, b1);
                            mma16816(acc[1][fm][fn], afr[1][fm], b0, b1);
                        } else {
                            mma16816(acc[0][fm][fn], afr[2][fm], b0, b1);
                            mma16816(acc[1][fm][fn], afr[0][fm], b0, b1);
                        }
                    }
            }
        }
    }

    const int rl = lane >> 2, cl = (lane & 3) * 2;
    #pragma unroll
    for (int fm = 0; fm < 2; fm++)
        #pragma unroll
        for (int fn = 0; fn < 8; fn++) {
            int m = m0 + warp_m + fm*16 + rl;
            int n = n0 + warp_n + fn*8 + cl;
            size_t off = (((size_t)sl*2 + b)*256 + m)*256 + n;
            float* c0 = acc[0][fm][fn];
            float* c1 = acc[1][fm][fn];
            *(float2*)(srp + off)         = make_float2(c0[0], c0[1]);
            *(float2*)(srp + off + 8*256) = make_float2(c0[2], c0[3]);
            *(float2*)(sip + off)         = make_float2(c1[0], c1[1]);
            *(float2*)(sip + off + 8*256) = make_float2(c1[2], c1[3]);
        }
}

// ---------------- softmax over query axis n, emits bf16 hi/lo --------------------
__global__ void __launch_bounds__(256) softmax_kernel(const float* __restrict__ srp,
                                                      const float* __restrict__ sip,
                                                      __nv_bfloat16* __restrict__ ahi,
                                                      __nv_bfloat16* __restrict__ alo)
{
    __shared__ float red[256];
    const int bm = blockIdx.x;
    const int b = bm >> 8, m = bm & 255;
    const int n = threadIdx.x;
    float sr = 0.f, si = 0.f;
    for (int sl = 0; sl < KSLICES; sl++) {
        size_t off = (((size_t)sl*2 + b)*256 + m)*256 + n;
        sr += srp[off]; si += sip[off];
    }
    float z = sqrtf(sr*sr + si*si);
    red[n] = z; __syncthreads();
    for (int st = 128; st > 0; st >>= 1) {
        if (n < st) red[n] = fmaxf(red[n], red[n+st]);
        __syncthreads();
    }
    float mx = red[0]; __syncthreads();
    float e = expf(z - mx);
    red[n] = e; __syncthreads();
    for (int st = 128; st > 0; st >>= 1) {
        if (n < st) red[n] += red[n+st];
        __syncthreads();
    }
    float a = e / red[0];
    float h = bf_hi(a);
    size_t off = ((size_t)b*256 + m)*256 + n;
    ahi[off] = __float2bfloat16_rn(h);
    alo[off] = __float2bfloat16_rn(a - h);
}

// ---------------- time-branch output (mma.sync split-3) --------------------------
// C[b][r][n] = sum_m V[b][r][m] * A[b][m][n]
__global__ void __launch_bounds__(256) out_time_mma_kernel(
    const __nv_bfloat16* __restrict__ vhi, const __nv_bfloat16* __restrict__ vlo,
    const __nv_bfloat16* __restrict__ ahi, const __nv_bfloat16* __restrict__ alo,
    float* __restrict__ out)
{
    __shared__ __align__(16) char sm[37888];  // Vh 10240, Vl 10240, Ah 8704, Al 8704
    const uint32_t sb = (uint32_t)__cvta_generic_to_shared(sm);
    const int tid = threadIdx.x, wid = tid >> 5, lane = tid & 31;
    const int r0 = blockIdx.x*128, n0 = blockIdx.y*128, b = blockIdx.z;
    const int warp_m = (wid >> 1) * 32, warp_n = (wid & 1) * 64;

    float acc[2][8][4];
    #pragma unroll
    for (int fm = 0; fm < 2; fm++)
        #pragma unroll
        for (int fn = 0; fn < 8; fn++)
            #pragma unroll
            for (int u = 0; u < 4; u++) acc[fm][fn][u] = 0.f;

    const int a_row = (lane & 7) + ((lane >> 3) & 1) * 8;
    const int a_u   = lane >> 4;
    const int bt_row = (lane & 7) + ((lane >> 3) & 1) * 8;
    const int bt_c   = (lane >> 4) * 8;

    for (int ch = 0; ch < 8; ch++) {
        const int m0c = ch*32;
        __syncthreads();
        // V tiles: [hl][row:128][k:32] pitch 80
        #pragma unroll
        for (int i = 0; i < 4; i++) {
            int idx = tid + i*256;
            int hl = idx >> 9, rem = idx & 511;
            int row = rem >> 2, u = rem & 3;
            uint4 v = *(const uint4*)((hl ? vlo : vhi)
                        + (size_t)(b*32768 + r0 + row)*256 + m0c + u*8);
            *(uint4*)(sm + hl*10240 + row*80 + u*16) = v;
        }
        // A tiles: [hl][k:32][n:128] pitch 272
        #pragma unroll
        for (int i = 0; i < 4; i++) {
            int idx = tid + i*256;
            int hl = idx >> 9, rem = idx & 511;
            int kk = rem >> 4, u = rem & 15;
            uint4 v = *(const uint4*)((hl ? alo : ahi)
                        + (size_t)(b*256 + m0c + kk)*256 + n0 + u*8);
            *(uint4*)(sm + 20480 + hl*8704 + kk*272 + u*16) = v;
        }
        __syncthreads();
        #pragma unroll
        for (int ks = 0; ks < 2; ks++) {
            uint32_t Vf[2][2][4];
            #pragma unroll
            for (int hl = 0; hl < 2; hl++)
                #pragma unroll
                for (int fm = 0; fm < 2; fm++)
                    ldm4(Vf[hl][fm], sb + hl*10240
                         + (warp_m + fm*16 + a_row)*80 + (ks*2 + a_u)*16);
            uint32_t Af[2][8][2];
            #pragma unroll
            for (int hl = 0; hl < 2; hl++)
                #pragma unroll
                for (int fn2 = 0; fn2 < 4; fn2++) {
                    uint32_t r[4];
                    ldm4t(r, sb + 20480 + hl*8704
                          + (ks*16 + bt_row)*272 + (warp_n + fn2*16 + bt_c)*2);
                    Af[hl][2*fn2+0][0] = r[0]; Af[hl][2*fn2+0][1] = r[1];
                    Af[hl][2*fn2+1][0] = r[2]; Af[hl][2*fn2+1][1] = r[3];
                }
            #pragma unroll
            for (int fm = 0; fm < 2; fm++)
                #pragma unroll
                for (int fn = 0; fn < 8; fn++) {
                    mma16816(acc[fm][fn], Vf[0][fm], Af[0][fn][0], Af[0][fn][1]);
                    mma16816(acc[fm][fn], Vf[0][fm], Af[1][fn][0], Af[1][fn][1]);
                    mma16816(acc[fm][fn], Vf[1][fm], Af[0][fn][0], Af[0][fn][1]);
                }
        }
    }
    const int rl = lane >> 2, cl = (lane & 3) * 2;
    #pragma unroll
    for (int fm = 0; fm < 2; fm++)
        #pragma unroll
        for (int fn = 0; fn < 8; fn++) {
            int r = r0 + warp_m + fm*16 + rl;
            int n = n0 + warp_n + fn*8 + cl;
            float* c4 = acc[fm][fn];
            *(float2*)(out + (size_t)(b*32768 + r)*256 + n)     = make_float2(c4[0], c4[1]);
            *(float2*)(out + (size_t)(b*32768 + r + 8)*256 + n) = make_float2(c4[2], c4[3]);
        }
}

// ---------------- freq-branch output (mma.sync split-3, accumulate) --------------
// of[plane][f][t] += sum_m A[b][m][f] * V[plane][m][t]
__global__ void __launch_bounds__(256) out_freq_mma_kernel(
    const __nv_bfloat16* __restrict__ vhi, const __nv_bfloat16* __restrict__ vlo,
    const __nv_bfloat16* __restrict__ ahi, const __nv_bfloat16* __restrict__ alo,
    float* __restrict__ out)
{
    __shared__ __align__(16) char sm[34816];  // Ah 8704, Al 8704, Vh 8704, Vl 8704
    const uint32_t sb = (uint32_t)__cvta_generic_to_shared(sm);
    const int tid = threadIdx.x, wid = tid >> 5, lane = tid & 31;
    const int f0 = (blockIdx.x >> 1)*128, t0 = (blockIdx.x & 1)*128;
    const int plane = blockIdx.y, b = plane >> 7;
    const int warp_f = (wid >> 1) * 32, warp_t = (wid & 1) * 64;
    const size_t vbase = (size_t)plane * SPAT;

    float acc[2][8][4];
    #pragma unroll
    for (int fm = 0; fm < 2; fm++)
        #pragma unroll
        for (int fn = 0; fn < 8; fn++)
            #pragma unroll
            for (int u = 0; u < 4; u++) acc[fm][fn][u] = 0.f;

    const int at_row = (lane & 7) + ((lane >> 4) << 3);   // trans-A: k row
    const int at_c   = ((lane >> 3) & 1) * 8;             // trans-A: m(f) col
    const int bt_row = (lane & 7) + ((lane >> 3) & 1) * 8;
    const int bt_c   = (lane >> 4) * 8;

    for (int ch = 0; ch < 8; ch++) {
        const int m0c = ch*32;
        __syncthreads();
        // A tiles: [hl][k:32][f:128] pitch 272
        #pragma unroll
        for (int i = 0; i < 4; i++) {
            int idx = tid + i*256;
            int hl = idx >> 9, rem = idx & 511;
            int kk = rem >> 4, u = rem & 15;
            uint4 v = *(const uint4*)((hl ? alo : ahi)
                        + (size_t)(b*256 + m0c + kk)*256 + f0 + u*8);
            *(uint4*)(sm + hl*8704 + kk*272 + u*16) = v;
        }
        // V tiles: [hl][k:32][t:128] pitch 272
        #pragma unroll
        for (int i = 0; i < 4; i++) {
            int idx = tid + i*256;
            int hl = idx >> 9, rem = idx & 511;
            int kk = rem >> 4, u = rem & 15;
            uint4 v = *(const uint4*)((hl ? vlo : vhi)
                        + vbase + (size_t)(m0c + kk)*256 + t0 + u*8);
            *(uint4*)(sm + 17408 + hl*8704 + kk*272 + u*16) = v;
        }
        __syncthreads();
        #pragma unroll
        for (int ks = 0; ks < 2; ks++) {
            uint32_t Afr[2][2][4];
            #pragma unroll
            for (int hl = 0; hl < 2; hl++)
                #pragma unroll
                for (int fm = 0; fm < 2; fm++)
                    ldm4t(Afr[hl][fm], sb + hl*8704
                          + (ks*16 + at_row)*272 + (warp_f + fm*16 + at_c)*2);
            uint32_t Vfr[2][8][2];
            #pragma unroll
            for (int hl = 0; hl < 2; hl++)
                #pragma unroll
                for (int fn2 = 0; fn2 < 4; fn2++) {
                    uint32_t r[4];
                    ldm4t(r, sb + 17408 + hl*8704
                          + (ks*16 + bt_row)*272 + (warp_t + fn2*16 + bt_c)*2);
                    Vfr[hl][2*fn2+0][0] = r[0]; Vfr[hl][2*fn2+0][1] = r[1];
                    Vfr[hl][2*fn2+1][0] = r[2]; Vfr[hl][2*fn2+1][1] = r[3];
                }
            #pragma unroll
            for (int fm = 0; fm < 2; fm++)
                #pragma unroll
                for (int fn = 0; fn < 8; fn++) {
                    mma16816(acc[fm][fn], Afr[0][fm], Vfr[0][fn][0], Vfr[0][fn][1]);
                    mma16816(acc[fm][fn], Afr[0][fm], Vfr[1][fn][0], Vfr[1][fn][1]);
                    mma16816(acc[fm][fn], Afr[1][fm], Vfr[0][fn][0], Vfr[0][fn][1]);
                }
        }
    }
    const int rl = lane >> 2, cl = (lane & 3) * 2;
    #pragma unroll
    for (int fm = 0; fm < 2; fm++)
        #pragma unroll
        for (int fn = 0; fn < 8; fn++) {
            int f = f0 + warp_f + fm*16 + rl;
            int t = t0 + warp_t + fn*8 + cl;
            float* c4 = acc[fm][fn];
            float* d0 = out + vbase + (size_t)f*256 + t;
            float* d1 = out + vbase + (size_t)(f + 8)*256 + t;
            float2 o0 = *(float2*)d0, o1 = *(float2*)d1;
            o0.x += c4[0]; o0.y += c4[1];
            o1.x += c4[2]; o1.y += c4[3];
            *(float2*)d0 = o0; *(float2*)d1 = o1;
        }
}

// ---------------- host launch ----------------------------------------------------
extern "C" void kernel_launch(void* const* d_in, const int* in_sizes, int n_in,
                              void* d_out, int out_size)
{
    const float* P    = (const float*)d_in[0];
    const float* Q    = (const float*)d_in[1];
    const float* W    = (const float*)d_in[2];
    // d_in[3] = bias: cancels exactly under BN mean subtraction -> unused
    const float* g    = (const float*)d_in[4];
    const float* beta = (const float*)d_in[5];
    float* out = (float*)d_out;

    float *qp, *kp, *vp, *srp, *sip, *scp, *shp, *partp;
    __nv_bfloat16 *qhi, *qlo, *khi, *klo, *vhi, *vlo, *pshi, *pslo, *qshi, *qslo,
                  *ahip, *alop, *wcp;
    cudaGetSymbolAddress((void**)&qp,  g_q);
    cudaGetSymbolAddress((void**)&kp,  g_k);
    cudaGetSymbolAddress((void**)&vp,  g_v);
    cudaGetSymbolAddress((void**)&qhi, g_qhi);
    cudaGetSymbolAddress((void**)&qlo, g_qlo);
    cudaGetSymbolAddress((void**)&khi, g_khi);
    cudaGetSymbolAddress((void**)&klo, g_klo);
    cudaGetSymbolAddress((void**)&vhi, g_vhi);
    cudaGetSymbolAddress((void**)&vlo, g_vlo);
    cudaGetSymbolAddress((void**)&pshi, g_pshi);
    cudaGetSymbolAddress((void**)&pslo, g_pslo);
    cudaGetSymbolAddress((void**)&qshi, g_qshi);
    cudaGetSymbolAddress((void**)&qslo, g_qslo);
    cudaGetSymbolAddress((void**)&ahip, g_ahi);
    cudaGetSymbolAddress((void**)&alop, g_alo);
    cudaGetSymbolAddress((void**)&wcp, g_wc);
    cudaGetSymbolAddress((void**)&partp, g_part);
    cudaGetSymbolAddress((void**)&srp, g_srp);
    cudaGetSymbolAddress((void**)&sip, g_sip);
    cudaGetSymbolAddress((void**)&scp, g_scale6);
    cudaGetSymbolAddress((void**)&shp, g_shift6);

    cudaFuncSetAttribute(conv_mma_kernel, cudaFuncAttributeMaxDynamicSharedMemorySize, CONV2_SMEM);
    cudaFuncSetAttribute(score_mma_kernel, cudaFuncAttributeMaxDynamicSharedMemorySize, SC2_SMEM);

    // one-time prep
    split_kernel<<<16384, 256>>>(P, pshi, pslo);
    split_kernel<<<16384, 256>>>(Q, qshi, qslo);
    wcomb_kernel<<<dim3(64, 6), 256>>>(W, wcp);

    auto conv_stats = [&](const __nv_bfloat16* xhi, const __nv_bfloat16* xlo,
                          int j, float* Y) {
        conv_mma_kernel<<<dim3(512, 2), 256, CONV2_SMEM>>>(xhi, xlo, wcp + (size_t)j*32768, Y, partp);
        stats_reduce_kernel<<<128, 256>>>(partp, g, beta, j, scp, shp);
    };

    // ---- time branch ----
    conv_stats(qshi, qslo, 0, qp);
    convert_T_kernel<<<dim3(8, 8, 256), 256>>>(qp, qhi, qlo, scp, shp, 0);
    conv_stats(pshi, pslo, 1, kp);
    convert_T_kernel<<<dim3(8, 8, 256), 256>>>(kp, khi, klo, scp, shp, 1);
    conv_stats(pshi, pslo, 2, vp);
    vconvert_kernel<<<16384, 256>>>(vp, vhi, vlo, scp, shp, 2);
    score_mma_kernel<<<dim3(2, 2, 64), 256, SC2_SMEM>>>(khi, klo, qhi, qlo, srp, sip);
    softmax_kernel<<<512, 256>>>(srp, sip, ahip, alop);
    out_time_mma_kernel<<<dim3(256, 2, 2), 256>>>(vhi, vlo, ahip, alop, out);

    // ---- freq branch ----
    conv_stats(qshi, qslo, 3, qp);
    convert_noT_kernel<<<dim3(32, 256), 256>>>(qp, qhi, qlo, scp, shp, 3);
    conv_stats(pshi, pslo, 4, kp);
    convert_noT_kernel<<<dim3(32, 256), 256>>>(kp, khi, klo, scp, shp, 4);
    conv_stats(pshi, pslo, 5, vp);
    vconvert_kernel<<<16384, 256>>>(vp, vhi, vlo, scp, shp, 5);
    score_mma_kernel<<<dim3(2, 2, 64), 256, SC2_SMEM>>>(khi, klo, qhi, qlo, srp, sip);
    softmax_kernel<<<512, 256>>>(srp, sip, ahip, alop);
    out_freq_mma_kernel<<<dim3(4, 256), 256>>>(vhi, vlo, ahip, alop, out);
}